// round 12
// baseline (speedup 1.0000x reference)
#include <cuda_runtime.h>
#include <cuda_fp16.h>
#include <cstdint>

constexpr int Bc  = 2;
constexpr int Sc  = 2048;
constexpr int Dc  = 1024;
constexpr int Hc  = 16;
constexpr int DKc = 64;
constexpr int Mtot = Bc * Sc;                       // 4096
constexpr size_t AMAT = (size_t)Mtot * Dc;          // 4M elems
constexpr size_t WMAT = (size_t)Dc * Dc;            // 1M elems
constexpr int TILE_B  = 16384;                      // 128 rows x 64 halfs x 2B
constexpr int KVT_B   = 8192;                       // 64 rows x 64 halfs x 2B

// Scratch (device globals) — all operands blocked + SW128-swizzled
__device__ __half g_xh[3 * AMAT], g_xl[3 * AMAT];   // split inputs (128-row tiles)
__device__ __half g_wh[4 * WMAT], g_wl[4 * WMAT];   // split weights [n][k] (128-row tiles)
__device__ __half g_oh[AMAT], g_ol[AMAT];           // attention out [b,s,d] (128-row tiles)
__device__ __half g_qh[AMAT], g_ql[AMAT];           // Q (x 0.125*log2e) 128-row tiles
__device__ __half g_kh[AMAT], g_kl[AMAT];           // K [bh, sblock] 64-row tiles
__device__ __half g_vh[AMAT], g_vl[AMAT];           // V [bh, sblock] 64-row tiles

// ---------------------------------------------------------------------------
// PTX helpers
// ---------------------------------------------------------------------------
__device__ __forceinline__ uint32_t smem_u32(const void* p) {
    uint32_t a;
    asm("{ .reg .u64 t; cvta.to.shared.u64 t, %1; cvt.u32.u64 %0, t; }" : "=r"(a) : "l"(p));
    return a;
}
__device__ __forceinline__ uint32_t sw128(uint32_t x) { return x ^ ((x >> 3) & 0x70); }

__device__ __forceinline__ void bulk_ld(uint32_t dst, const void* src, uint32_t bytes,
                                        uint32_t mbar) {
    asm volatile(
        "cp.async.bulk.shared::cluster.global.mbarrier::complete_tx::bytes "
        "[%0], [%1], %2, [%3];"
        :: "r"(dst), "l"(src), "r"(bytes), "r"(mbar) : "memory");
}
__device__ __forceinline__ void mbar_init(uint32_t a, uint32_t cnt) {
    asm volatile("mbarrier.init.shared.b64 [%0], %1;" :: "r"(a), "r"(cnt) : "memory");
}
__device__ __forceinline__ void mbar_expect_tx(uint32_t a, uint32_t bytes) {
    asm volatile("mbarrier.arrive.expect_tx.shared.b64 _, [%0], %1;"
                 :: "r"(a), "r"(bytes) : "memory");
}
__device__ __forceinline__ void mbar_arrive(uint32_t a) {
    asm volatile("mbarrier.arrive.shared.b64 _, [%0];" :: "r"(a) : "memory");
}
__device__ __forceinline__ void mwait(uint32_t mbar, uint32_t parity) {
    asm volatile(
        "{\n\t.reg .pred P;\n\t"
        "WL%=:\n\t"
        "mbarrier.try_wait.parity.acquire.cta.shared::cta.b64 P, [%0], %1, 0x989680;\n\t"
        "@!P bra WL%=;\n\t}"
        :: "r"(mbar), "r"(parity) : "memory");
}
__device__ __forceinline__ void fence_async_sh() {
    asm volatile("fence.proxy.async.shared::cta;" ::: "memory");
}

__device__ __forceinline__ void ldsm4(uint32_t r[4], uint32_t addr) {
    asm volatile("ldmatrix.sync.aligned.m8n8.x4.shared.b16 {%0,%1,%2,%3}, [%4];"
                 : "=r"(r[0]), "=r"(r[1]), "=r"(r[2]), "=r"(r[3]) : "r"(addr));
}
__device__ __forceinline__ void ldsm4t(uint32_t r[4], uint32_t addr) {
    asm volatile("ldmatrix.sync.aligned.m8n8.x4.trans.shared.b16 {%0,%1,%2,%3}, [%4];"
                 : "=r"(r[0]), "=r"(r[1]), "=r"(r[2]), "=r"(r[3]) : "r"(addr));
}
__device__ __forceinline__ void mmaf16(float* c, const uint32_t a[4],
                                       uint32_t b0, uint32_t b1) {
    asm volatile("mma.sync.aligned.m16n8k16.row.col.f32.f16.f16.f32 "
                 "{%0,%1,%2,%3}, {%4,%5,%6,%7}, {%8,%9}, {%0,%1,%2,%3};"
                 : "+f"(c[0]), "+f"(c[1]), "+f"(c[2]), "+f"(c[3])
                 : "r"(a[0]), "r"(a[1]), "r"(a[2]), "r"(a[3]), "r"(b0), "r"(b1));
}
__device__ __forceinline__ uint32_t packh2(__half a, __half b) {
    __half2 h = __halves2half2(a, b);
    return *(uint32_t*)&h;
}

// ---------------------------------------------------------------------------
// Split-fp16 mma.sync GEMM, producer-warp pipeline.
// Retiled for occupancy: CTA 128(M) x 64(N), BK=64, 2 stages x 48KB = 96KB
// → 2 CTAs/SM (regs capped via launch_bounds(288,2)).
// Stage layout: Ahi 0 | Alo 16K | Bhi 32K | Blo 40K.
// B operand = contiguous 8KB half of a 128-row weight tile (swizzle is
// row&7-relative, so sub-tiles are self-similar).
// MODE 0: fp32 row-major. MODE 1: Q blocked (scaled). MODE 2: K/V blocked.
// ---------------------------------------------------------------------------
constexpr int PNS    = 2;
constexpr int PST_B  = 49152;            // 48KB per stage
constexpr int PSMEM  = PNS * PST_B;      // 98304

template <int MODE>
__device__ __forceinline__ void gemm_mma(const __half* __restrict__ Ahi,
                                         const __half* __restrict__ Alo,
                                         const __half* __restrict__ Bhi,
                                         const __half* __restrict__ Blo,
                                         const float* __restrict__ bias,
                                         float* __restrict__ Cf,
                                         __half* __restrict__ Ch,
                                         __half* __restrict__ Cl,
                                         float scale) {
    extern __shared__ char smemraw[];
    const uint32_t sb = smem_u32(smemraw);
    __shared__ uint64_t mbarS[2 * PNS];
    uint32_t mbF[PNS], mbE[PNS];
#pragma unroll
    for (int i = 0; i < PNS; i++) {
        mbF[i] = smem_u32(&mbarS[i]);
        mbE[i] = smem_u32(&mbarS[PNS + i]);
    }

    const int tid  = threadIdx.x;
    const int wid  = tid >> 5;
    const int lane = tid & 31;
    const int m0   = blockIdx.y << 7;
    const int n0   = blockIdx.x << 6;

    if (tid == 0) {
#pragma unroll
        for (int i = 0; i < PNS; i++) {
            mbar_init(mbF[i], 1);
            mbar_init(mbE[i], 8);
        }
        fence_async_sh();
    }
    __syncthreads();

    const int NIT = Dc / 64;   // 16

    if (wid == 8) {
        if (lane == 0) {
            for (int it = 0; it < NIT; ++it) {
                const int s = it & 1;
                const int u = it >> 1;
                if (u > 0) mwait(mbE[s], (u - 1) & 1);
                const uint32_t stb = sb + (uint32_t)s * PST_B;
                const size_t at = ((size_t)blockIdx.y * 16 + it) * TILE_B;
                const size_t bt = ((size_t)((n0 >> 7) * 16 + it)) * TILE_B +
                                  (size_t)((n0 & 64) << 7);
                mbar_expect_tx(mbF[s], 2 * TILE_B + 2 * KVT_B);
                bulk_ld(stb,          (const char*)Ahi + at, TILE_B, mbF[s]);
                bulk_ld(stb + 16384u, (const char*)Alo + at, TILE_B, mbF[s]);
                bulk_ld(stb + 32768u, (const char*)Bhi + bt, KVT_B, mbF[s]);
                bulk_ld(stb + 40960u, (const char*)Blo + bt, KVT_B, mbF[s]);
            }
        }
        return;
    }

    const int g    = lane >> 2;
    const int tg   = lane & 3;
    const int wm   = wid & 3;            // 4 warps over M (32 rows each)
    const int wn   = wid >> 2;           // 2 warps over N (32 cols each)
    const int l16  = lane & 15;
    const int hi16 = (lane >> 4) * 16;

    float acc[2][4][4];
#pragma unroll
    for (int i = 0; i < 2; i++)
#pragma unroll
        for (int j = 0; j < 4; j++)
#pragma unroll
            for (int c = 0; c < 4; c++) acc[i][j][c] = 0.0f;

    for (int it = 0; it < NIT; ++it) {
        const int s = it & 1;
        const int u = it >> 1;
        mwait(mbF[s], u & 1);
        const uint32_t stb = sb + (uint32_t)s * PST_B;

#pragma unroll
        for (int kt = 0; kt < 4; ++kt) {
            uint32_t ah[2][4], al[2][4];
#pragma unroll
            for (int mt = 0; mt < 2; mt++) {
                const int row = wm * 32 + mt * 16 + l16;
                const uint32_t off = (uint32_t)(row * 128) +
                    (((uint32_t)(kt * 32 + hi16)) ^ ((uint32_t)(row & 7) << 4));
                ldsm4(ah[mt], stb + off);
                ldsm4(al[mt], stb + 16384u + off);
            }
#pragma unroll
            for (int np = 0; np < 2; ++np) {
                const int row = wn * 32 + np * 16 + l16;
                const uint32_t off = (uint32_t)(row * 128) +
                    (((uint32_t)(kt * 32 + hi16)) ^ ((uint32_t)(row & 7) << 4));
                uint32_t bh4[4], bl4[4];
                ldsm4(bh4, stb + 32768u + off);
                ldsm4(bl4, stb + 40960u + off);
#pragma unroll
                for (int mt = 0; mt < 2; mt++)
#pragma unroll
                    for (int e = 0; e < 2; e++) {
                        float* c = acc[mt][np * 2 + e];
                        mmaf16(c, ah[mt], bh4[e], bh4[2 + e]);
                        mmaf16(c, ah[mt], bl4[e], bl4[2 + e]);
                        mmaf16(c, al[mt], bh4[e], bh4[2 + e]);
                    }
            }
        }
        __syncwarp();
        if (lane == 0) mbar_arrive(mbE[s]);
    }

    // Epilogue
#pragma unroll
    for (int mt = 0; mt < 2; ++mt) {
#pragma unroll
        for (int nt = 0; nt < 4; ++nt) {
            const int n   = n0 + wn * 32 + nt * 8 + tg * 2;
            const float b0v = bias[n];
            const float b1v = bias[n + 1];
#pragma unroll
            for (int hh = 0; hh < 2; ++hh) {
                const int m  = m0 + wm * 32 + mt * 16 + g + hh * 8;
                const float v0 = acc[mt][nt][hh * 2 + 0] + b0v;
                const float v1 = acc[mt][nt][hh * 2 + 1] + b1v;
                if (MODE == 0) {
                    *(float2*)&Cf[(size_t)m * Dc + n] = make_float2(v0, v1);
                } else {
                    const float s0 = v0 * scale;
                    const float s1 = v1 * scale;
                    const int bb = m >> 11;
                    const int ss = m & (Sc - 1);
                    const int hd = n >> 6;
                    const int dk = n & 63;
                    const int bh = bb * Hc + hd;
                    const __half h0 = __float2half_rn(s0);
                    const __half h1 = __float2half_rn(s1);
                    size_t byteoff;
                    if (MODE == 1) {
                        byteoff = ((size_t)(bh * 16 + (ss >> 7))) * TILE_B +
                                  sw128((uint32_t)((ss & 127) * 128 + dk * 2));
                    } else {
                        byteoff = ((size_t)(bh * 32 + (ss >> 6))) * KVT_B +
                                  sw128((uint32_t)((ss & 63) * 128 + dk * 2));
                    }
                    *(uint32_t*)((char*)Ch + byteoff) = packh2(h0, h1);
                    *(uint32_t*)((char*)Cl + byteoff) =
                        packh2(__float2half_rn(s0 - __half2float(h0)),
                               __float2half_rn(s1 - __half2float(h1)));
                }
            }
        }
    }
}

__global__ __launch_bounds__(288, 2) void qkv_mma_kernel(
    const float* __restrict__ bq, const float* __restrict__ bk,
    const float* __restrict__ bv) {
    const int z = blockIdx.z;
    const __half* Ahi = g_xh + (size_t)z * AMAT;
    const __half* Alo = g_xl + (size_t)z * AMAT;
    const __half* Bhi = g_wh + (size_t)z * WMAT;
    const __half* Blo = g_wl + (size_t)z * WMAT;
    if (z == 0)   // Q pre-scaled by (1/8)*log2(e): softmax uses exp2
        gemm_mma<1>(Ahi, Alo, Bhi, Blo, bq, nullptr, g_qh, g_ql,
                    0.125f * 1.4426950408889634f);
    else if (z == 1)
        gemm_mma<2>(Ahi, Alo, Bhi, Blo, bk, nullptr, g_kh, g_kl, 1.0f);
    else
        gemm_mma<2>(Ahi, Alo, Bhi, Blo, bv, nullptr, g_vh, g_vl, 1.0f);
}

__global__ __launch_bounds__(288, 2) void out_mma_kernel(
    const float* __restrict__ bo, float* __restrict__ out) {
    gemm_mma<0>(g_oh, g_ol, g_wh + 3 * WMAT, g_wl + 3 * WMAT, bo,
                out, nullptr, nullptr, 1.0f);
}

// ---------------------------------------------------------------------------
// Conversions → blocked + SW128-swizzled 128-row tile layout (proven R8).
// ---------------------------------------------------------------------------
__global__ __launch_bounds__(256) void conv_act_kernel(
    const float* __restrict__ q, const float* __restrict__ k,
    const float* __restrict__ v) {
    const int z = blockIdx.y;
    const float* src = (z == 0) ? q : (z == 1) ? k : v;
    const size_t i4 = ((size_t)blockIdx.x * 256 + threadIdx.x) * 4;
    const float4 x = *(const float4*)(src + i4);
    const __half h0 = __float2half_rn(x.x), h1 = __float2half_rn(x.y);
    const __half h2 = __float2half_rn(x.z), h3 = __float2half_rn(x.w);
    uint2 hv, lv;
    hv.x = packh2(h0, h1);
    hv.y = packh2(h2, h3);
    lv.x = packh2(__float2half_rn(x.x - __half2float(h0)),
                  __float2half_rn(x.y - __half2float(h1)));
    lv.y = packh2(__float2half_rn(x.z - __half2float(h2)),
                  __float2half_rn(x.w - __half2float(h3)));
    const int m  = (int)(i4 >> 10);
    const int kk = (int)(i4 & 1023);
    const size_t tile = (size_t)z * 512 + (size_t)(m >> 7) * 16 + (kk >> 6);
    const uint32_t inner = sw128((uint32_t)((m & 127) * 128 + (kk & 63) * 2));
    *(uint2*)((char*)g_xh + tile * TILE_B + inner) = hv;
    *(uint2*)((char*)g_xl + tile * TILE_B + inner) = lv;
}

__global__ __launch_bounds__(256) void conv_w_kernel(
    const float* __restrict__ Wq, const float* __restrict__ Wk,
    const float* __restrict__ Wv, const float* __restrict__ Wo) {
    __shared__ float t[32][33];
    const int z = blockIdx.z;
    const float* W = (z == 0) ? Wq : (z == 1) ? Wk : (z == 2) ? Wv : Wo;
    const int k0 = blockIdx.y << 5;
    const int n0 = blockIdx.x << 5;
    const int tx = threadIdx.x & 31;
    const int ty = threadIdx.x >> 5;
#pragma unroll
    for (int j = 0; j < 4; j++)
        t[ty + j * 8][tx] = W[(size_t)(k0 + ty + j * 8) * Dc + n0 + tx];
    __syncthreads();
#pragma unroll
    for (int j = 0; j < 4; j++) {
        const float val = t[tx][ty + j * 8];
        const __half hv = __float2half_rn(val);
        const int n = n0 + ty + j * 8;
        const int kk = k0 + tx;
        const size_t tile = (size_t)z * 128 + (size_t)(n >> 7) * 16 + (kk >> 6);
        const uint32_t inner = sw128((uint32_t)((n & 127) * 128 + (kk & 63) * 2));
        *(__half*)((char*)g_wh + tile * TILE_B + inner) = hv;
        *(__half*)((char*)g_wl + tile * TILE_B + inner) =
            __float2half_rn(val - __half2float(hv));
    }
}

// ---------------------------------------------------------------------------
// Flash attention, mma.sync fp16 3-term, producer-warp pipeline, maxless
// softmax (exp2, Q carries 0.125*log2e). NEW: software-pipelined mainloop —
// S-MMA(kb+1) is issued between softmax/pack(kb) and PV(kb) into a second
// accumulator buffer, letting ptxas interleave softmax MUFU/CVT with HMMA.
// ---------------------------------------------------------------------------
constexpr int ANS = 4;
constexpr int ATT_SMEM = 32768 + ANS * 32768;   // 163840

__global__ __launch_bounds__(288, 1) void attn_mma_kernel() {
    extern __shared__ char smemraw[];
    const uint32_t sb = smem_u32(smemraw);
    __shared__ uint64_t mbarS[2 * ANS + 1];
    uint32_t mbF[ANS], mbE[ANS];
#pragma unroll
    for (int i = 0; i < ANS; i++) {
        mbF[i] = smem_u32(&mbarS[i]);
        mbE[i] = smem_u32(&mbarS[ANS + i]);
    }
    const uint32_t mbQ = smem_u32(&mbarS[2 * ANS]);

    const int tid  = threadIdx.x;
    const int wid  = tid >> 5;
    const int lane = tid & 31;
    const int bh   = blockIdx.y;
    const int q0b  = blockIdx.x;

    if (tid == 0) {
#pragma unroll
        for (int i = 0; i < ANS; i++) {
            mbar_init(mbF[i], 1);
            mbar_init(mbE[i], 8);
        }
        mbar_init(mbQ, 1);
        fence_async_sh();
    }
    __syncthreads();

    if (wid == 8) {
        if (lane == 0) {
            const size_t qt = ((size_t)(bh * 16 + q0b)) * TILE_B;
            mbar_expect_tx(mbQ, 2 * TILE_B);
            bulk_ld(sb,           (char*)g_qh + qt, TILE_B, mbQ);
            bulk_ld(sb + TILE_B,  (char*)g_ql + qt, TILE_B, mbQ);
            for (int kb = 0; kb < 32; ++kb) {
                const int s = kb & (ANS - 1);
                const int u = kb >> 2;
                if (u > 0) mwait(mbE[s], (u - 1) & 1);
                const uint32_t stb = sb + 32768u + (uint32_t)s * 32768u;
                const size_t t = ((size_t)(bh * 32 + kb)) * KVT_B;
                mbar_expect_tx(mbF[s], 4 * KVT_B);
                bulk_ld(stb,              (char*)g_kh + t, KVT_B, mbF[s]);
                bulk_ld(stb + KVT_B,      (char*)g_kl + t, KVT_B, mbF[s]);
                bulk_ld(stb + 2 * KVT_B,  (char*)g_vh + t, KVT_B, mbF[s]);
                bulk_ld(stb + 3 * KVT_B,  (char*)g_vl + t, KVT_B, mbF[s]);
            }
        }
        return;
    }

    const int g    = lane >> 2;
    const int tg   = lane & 3;
    const int l16  = lane & 15;
    const int hi16 = (lane >> 4) * 16;

    // Q fragments
    mwait(mbQ, 0);
    uint32_t qh[4][4], ql[4][4];
    {
        const int row = wid * 16 + l16;
#pragma unroll
        for (int kt = 0; kt < 4; kt++) {
            const uint32_t off = (uint32_t)(row * 128) +
                (((uint32_t)(kt * 32 + hi16)) ^ ((uint32_t)(row & 7) << 4));
            ldsm4(qh[kt], sb + off);
            ldsm4(ql[kt], sb + TILE_B + off);
        }
    }

    // S = Q @ K^T (3-term) into a given accumulator buffer
    auto smma = [&](uint32_t stb, float (*sacc)[4]) {
#pragma unroll
        for (int nt = 0; nt < 8; nt++)
#pragma unroll
            for (int c = 0; c < 4; c++) sacc[nt][c] = 0.0f;
#pragma unroll
        for (int kt = 0; kt < 4; kt++) {
#pragma unroll
            for (int np = 0; np < 4; np++) {
                const int row = np * 16 + l16;
                const uint32_t off = (uint32_t)(row * 128) +
                    (((uint32_t)(kt * 32 + hi16)) ^ ((uint32_t)(row & 7) << 4));
                uint32_t kh4[4], kl4[4];
                ldsm4(kh4, stb + off);
                ldsm4(kl4, stb + KVT_B + off);
#pragma unroll
                for (int e = 0; e < 2; e++) {
                    float* c = sacc[np * 2 + e];
                    mmaf16(c, qh[kt], kh4[e], kh4[2 + e]);
                    mmaf16(c, qh[kt], kl4[e], kl4[2 + e]);
                    mmaf16(c, ql[kt], kh4[e], kh4[2 + e]);
                }
            }
        }
    };

    float lrow[2] = {0.0f, 0.0f};
    float O[8][4];
#pragma unroll
    for (int nt = 0; nt < 8; nt++)
#pragma unroll
        for (int c = 0; c < 4; c++) O[nt][c] = 0.0f;

    float sacc[2][8][4];

    // Prologue: S(0)
    mwait(mbF[0], 0);
    smma(sb + 32768u, sacc[0]);

    for (int kb = 0; kb < 32; ++kb) {
        const int cur = kb & 1;
        const int s   = kb & (ANS - 1);
        const uint32_t stb = sb + 32768u + (uint32_t)s * 32768u;

        // ---- softmax numerators (no max subtraction) ----
#pragma unroll
        for (int r = 0; r < 2; r++) {
            float rs = 0.0f;
#pragma unroll
            for (int nt = 0; nt < 8; nt++) {
                const float e0 = exp2f(sacc[cur][nt][r * 2]);
                const float e1 = exp2f(sacc[cur][nt][r * 2 + 1]);
                sacc[cur][nt][r * 2]     = e0;
                sacc[cur][nt][r * 2 + 1] = e1;
                rs += e0 + e1;
            }
            rs += __shfl_xor_sync(0xffffffffu, rs, 1);
            rs += __shfl_xor_sync(0xffffffffu, rs, 2);
            lrow[r] += rs;
        }

        // ---- pack P (hi/lo) as A fragments ----
        uint32_t pph[4][4], ppl[4][4];
#pragma unroll
        for (int kt = 0; kt < 4; kt++) {
            const float* s0 = sacc[cur][kt * 2];
            const float* s1 = sacc[cur][kt * 2 + 1];
            const float v[4][2] = {
                { s0[0], s0[1] }, { s0[2], s0[3] },
                { s1[0], s1[1] }, { s1[2], s1[3] },
            };
#pragma unroll
            for (int a = 0; a < 4; a++) {
                const __half h0 = __float2half_rn(v[a][0]);
                const __half h1 = __float2half_rn(v[a][1]);
                pph[kt][a] = packh2(h0, h1);
                ppl[kt][a] = packh2(__float2half_rn(v[a][0] - __half2float(h0)),
                                    __float2half_rn(v[a][1] - __half2float(h1)));
            }
        }

        // ---- prefetch next S (independent HMMA stream; ptxas interleaves
        //      it with the softmax/pack arithmetic above) ----
        if (kb + 1 < 32) {
            const int s1i = (kb + 1) & (ANS - 1);
            mwait(mbF[s1i], ((kb + 1) >> 2) & 1);
            smma(sb + 32768u + (uint32_t)s1i * 32768u, sacc[cur ^ 1]);
        }

        // ---- O += P @ V (3-term), V via ldmatrix.trans ----
#pragma unroll
        for (int kt = 0; kt < 4; kt++) {
#pragma unroll
            for (int np = 0; np < 4; np++) {
                const int row = kt * 16 + l16;
                const uint32_t off = (uint32_t)(row * 128) +
                    (((uint32_t)(np * 32 + hi16)) ^ ((uint32_t)(row & 7) << 4));
                uint32_t vh4[4], vl4[4];
                ldsm4t(vh4, stb + 2 * KVT_B + off);
                ldsm4t(vl4, stb + 3 * KVT_B + off);
#pragma unroll
                for (int e = 0; e < 2; e++) {
                    float* c = O[np * 2 + e];
                    mmaf16(c, pph[kt], vh4[e * 2], vh4[e * 2 + 1]);
                    mmaf16(c, pph[kt], vl4[e * 2], vl4[e * 2 + 1]);
                    mmaf16(c, ppl[kt], vh4[e * 2], vh4[e * 2 + 1]);
                }
            }
        }
        __syncwarp();
        if (lane == 0) mbar_arrive(mbE[s]);
    }

    // ---- write O as split fp16 into BLOCKED layout (out-proj A operand) ----
    const int b = bh >> 4;
    const int h = bh & 15;
#pragma unroll
    for (int r = 0; r < 2; r++) {
        const float inv = 1.0f / lrow[r];
        const int row = q0b * 128 + wid * 16 + g + r * 8;
        const int m   = b * Sc + row;
        const size_t tbase = ((size_t)(m >> 7) * 16 + h) * TILE_B;
        const uint32_t rbase = (uint32_t)((m & 127) * 128);
        const uint32_t xm    = (uint32_t)((m & 7) << 4);
#pragma unroll
        for (int nt = 0; nt < 8; nt++) {
            const int c = nt * 8 + tg * 2;
            const uint32_t inner = rbase + (((uint32_t)(c * 2)) ^ xm);
            const float v0 = O[nt][r * 2]     * inv;
            const float v1 = O[nt][r * 2 + 1] * inv;
            const __half h0 = __float2half_rn(v0);
            const __half h1 = __float2half_rn(v1);
            *(uint32_t*)((char*)g_oh + tbase + inner) = packh2(h0, h1);
            *(uint32_t*)((char*)g_ol + tbase + inner) =
                packh2(__float2half_rn(v0 - __half2float(h0)),
                       __float2half_rn(v1 - __half2float(h1)));
        }
    }
}

// ---------------------------------------------------------------------------
// Inputs: q,k,v,mask,Wq,bq,Wk,bk,Wv,bv,Wo,bo (mask inert, as in reference)
// ---------------------------------------------------------------------------
extern "C" void kernel_launch(void* const* d_in, const int* in_sizes, int n_in,
                              void* d_out, int out_size) {
    (void)in_sizes; (void)n_in; (void)out_size;
    const float* q  = (const float*)d_in[0];
    const float* k  = (const float*)d_in[1];
    const float* v  = (const float*)d_in[2];
    const float* Wq = (const float*)d_in[4];
    const float* bq = (const float*)d_in[5];
    const float* Wk = (const float*)d_in[6];
    const float* bk = (const float*)d_in[7];
    const float* Wv = (const float*)d_in[8];
    const float* bv = (const float*)d_in[9];
    const float* Wo = (const float*)d_in[10];
    const float* bo = (const float*)d_in[11];
    float* out = (float*)d_out;

    static bool attr_set = false;
    if (!attr_set) {
        cudaFuncSetAttribute(attn_mma_kernel,
                             cudaFuncAttributeMaxDynamicSharedMemorySize, ATT_SMEM);
        cudaFuncSetAttribute(qkv_mma_kernel,
                             cudaFuncAttributeMaxDynamicSharedMemorySize, PSMEM);
        cudaFuncSetAttribute(out_mma_kernel,
                             cudaFuncAttributeMaxDynamicSharedMemorySize, PSMEM);
        attr_set = true;
    }

    conv_act_kernel<<<dim3((unsigned)(AMAT / 1024), 3), 256>>>(q, k, v);
    conv_w_kernel<<<dim3(32, 32, 4), 256>>>(Wq, Wk, Wv, Wo);

    qkv_mma_kernel<<<dim3(16, 32, 3), 288, PSMEM>>>(bq, bk, bv);
    attn_mma_kernel<<<dim3(16, 32), 288, ATT_SMEM>>>();
    out_mma_kernel<<<dim3(16, 32), 288, PSMEM>>>(bo, out);
}

// round 13
// speedup vs baseline: 1.1003x; 1.1003x over previous
#include <cuda_runtime.h>
#include <cuda_fp16.h>
#include <cstdint>

constexpr int Bc  = 2;
constexpr int Sc  = 2048;
constexpr int Dc  = 1024;
constexpr int Hc  = 16;
constexpr int DKc = 64;
constexpr int Mtot = Bc * Sc;                       // 4096
constexpr size_t AMAT = (size_t)Mtot * Dc;          // 4M elems
constexpr size_t WMAT = (size_t)Dc * Dc;            // 1M elems
constexpr int TILE_B  = 16384;                      // 128 rows x 64 halfs x 2B
constexpr int KVT_B   = 8192;                       // 64 rows x 64 halfs x 2B

// Scratch (device globals) — all operands blocked + SW128-swizzled
__device__ __half g_xh[3 * AMAT], g_xl[3 * AMAT];   // split inputs (128-row tiles)
__device__ __half g_wh[4 * WMAT], g_wl[4 * WMAT];   // split weights [n][k] (128-row tiles)
__device__ __half g_oh[AMAT], g_ol[AMAT];           // attention out [b,s,d] (128-row tiles)
__device__ __half g_qh[AMAT], g_ql[AMAT];           // Q (x 0.125*log2e) 128-row tiles
__device__ __half g_kh[AMAT], g_kl[AMAT];           // K [bh, sblock] 64-row tiles
__device__ __half g_vh[AMAT], g_vl[AMAT];           // V [bh, sblock] 64-row tiles

// ---------------------------------------------------------------------------
// PTX helpers
// ---------------------------------------------------------------------------
__device__ __forceinline__ uint32_t smem_u32(const void* p) {
    uint32_t a;
    asm("{ .reg .u64 t; cvta.to.shared.u64 t, %1; cvt.u32.u64 %0, t; }" : "=r"(a) : "l"(p));
    return a;
}
__device__ __forceinline__ uint32_t sw128(uint32_t x) { return x ^ ((x >> 3) & 0x70); }

__device__ __forceinline__ void bulk_ld(uint32_t dst, const void* src, uint32_t bytes,
                                        uint32_t mbar) {
    asm volatile(
        "cp.async.bulk.shared::cluster.global.mbarrier::complete_tx::bytes "
        "[%0], [%1], %2, [%3];"
        :: "r"(dst), "l"(src), "r"(bytes), "r"(mbar) : "memory");
}
__device__ __forceinline__ void mbar_init(uint32_t a, uint32_t cnt) {
    asm volatile("mbarrier.init.shared.b64 [%0], %1;" :: "r"(a), "r"(cnt) : "memory");
}
__device__ __forceinline__ void mbar_expect_tx(uint32_t a, uint32_t bytes) {
    asm volatile("mbarrier.arrive.expect_tx.shared.b64 _, [%0], %1;"
                 :: "r"(a), "r"(bytes) : "memory");
}
__device__ __forceinline__ void mbar_arrive(uint32_t a) {
    asm volatile("mbarrier.arrive.shared.b64 _, [%0];" :: "r"(a) : "memory");
}
__device__ __forceinline__ void mwait(uint32_t mbar, uint32_t parity) {
    asm volatile(
        "{\n\t.reg .pred P;\n\t"
        "WL%=:\n\t"
        "mbarrier.try_wait.parity.acquire.cta.shared::cta.b64 P, [%0], %1, 0x989680;\n\t"
        "@!P bra WL%=;\n\t}"
        :: "r"(mbar), "r"(parity) : "memory");
}
__device__ __forceinline__ void fence_async_sh() {
    asm volatile("fence.proxy.async.shared::cta;" ::: "memory");
}

__device__ __forceinline__ void ldsm4(uint32_t r[4], uint32_t addr) {
    asm volatile("ldmatrix.sync.aligned.m8n8.x4.shared.b16 {%0,%1,%2,%3}, [%4];"
                 : "=r"(r[0]), "=r"(r[1]), "=r"(r[2]), "=r"(r[3]) : "r"(addr));
}
__device__ __forceinline__ void ldsm4t(uint32_t r[4], uint32_t addr) {
    asm volatile("ldmatrix.sync.aligned.m8n8.x4.trans.shared.b16 {%0,%1,%2,%3}, [%4];"
                 : "=r"(r[0]), "=r"(r[1]), "=r"(r[2]), "=r"(r[3]) : "r"(addr));
}
__device__ __forceinline__ void mmaf16(float* c, const uint32_t a[4],
                                       uint32_t b0, uint32_t b1) {
    asm volatile("mma.sync.aligned.m16n8k16.row.col.f32.f16.f16.f32 "
                 "{%0,%1,%2,%3}, {%4,%5,%6,%7}, {%8,%9}, {%0,%1,%2,%3};"
                 : "+f"(c[0]), "+f"(c[1]), "+f"(c[2]), "+f"(c[3])
                 : "r"(a[0]), "r"(a[1]), "r"(a[2]), "r"(a[3]), "r"(b0), "r"(b1));
}
__device__ __forceinline__ uint32_t packh2(__half a, __half b) {
    __half2 h = __halves2half2(a, b);
    return *(uint32_t*)&h;
}

// ---------------------------------------------------------------------------
// Split-fp16 mma.sync GEMM, producer-warp pipeline (R12 WIN — kept).
// CTA 128(M) x 64(N), BK=64, 2 stages x 48KB = 96KB → 2 CTAs/SM.
// MODE 0: fp32 row-major. MODE 1: Q blocked (scaled). MODE 2: K/V blocked.
// ---------------------------------------------------------------------------
constexpr int PNS    = 2;
constexpr int PST_B  = 49152;            // 48KB per stage
constexpr int PSMEM  = PNS * PST_B;      // 98304

template <int MODE>
__device__ __forceinline__ void gemm_mma(const __half* __restrict__ Ahi,
                                         const __half* __restrict__ Alo,
                                         const __half* __restrict__ Bhi,
                                         const __half* __restrict__ Blo,
                                         const float* __restrict__ bias,
                                         float* __restrict__ Cf,
                                         __half* __restrict__ Ch,
                                         __half* __restrict__ Cl,
                                         float scale) {
    extern __shared__ char smemraw[];
    const uint32_t sb = smem_u32(smemraw);
    __shared__ uint64_t mbarS[2 * PNS];
    uint32_t mbF[PNS], mbE[PNS];
#pragma unroll
    for (int i = 0; i < PNS; i++) {
        mbF[i] = smem_u32(&mbarS[i]);
        mbE[i] = smem_u32(&mbarS[PNS + i]);
    }

    const int tid  = threadIdx.x;
    const int wid  = tid >> 5;
    const int lane = tid & 31;
    const int m0   = blockIdx.y << 7;
    const int n0   = blockIdx.x << 6;

    if (tid == 0) {
#pragma unroll
        for (int i = 0; i < PNS; i++) {
            mbar_init(mbF[i], 1);
            mbar_init(mbE[i], 8);
        }
        fence_async_sh();
    }
    __syncthreads();

    const int NIT = Dc / 64;   // 16

    if (wid == 8) {
        if (lane == 0) {
            for (int it = 0; it < NIT; ++it) {
                const int s = it & 1;
                const int u = it >> 1;
                if (u > 0) mwait(mbE[s], (u - 1) & 1);
                const uint32_t stb = sb + (uint32_t)s * PST_B;
                const size_t at = ((size_t)blockIdx.y * 16 + it) * TILE_B;
                const size_t bt = ((size_t)((n0 >> 7) * 16 + it)) * TILE_B +
                                  (size_t)((n0 & 64) << 7);
                mbar_expect_tx(mbF[s], 2 * TILE_B + 2 * KVT_B);
                bulk_ld(stb,          (const char*)Ahi + at, TILE_B, mbF[s]);
                bulk_ld(stb + 16384u, (const char*)Alo + at, TILE_B, mbF[s]);
                bulk_ld(stb + 32768u, (const char*)Bhi + bt, KVT_B, mbF[s]);
                bulk_ld(stb + 40960u, (const char*)Blo + bt, KVT_B, mbF[s]);
            }
        }
        return;
    }

    const int g    = lane >> 2;
    const int tg   = lane & 3;
    const int wm   = wid & 3;            // 4 warps over M (32 rows each)
    const int wn   = wid >> 2;           // 2 warps over N (32 cols each)
    const int l16  = lane & 15;
    const int hi16 = (lane >> 4) * 16;

    float acc[2][4][4];
#pragma unroll
    for (int i = 0; i < 2; i++)
#pragma unroll
        for (int j = 0; j < 4; j++)
#pragma unroll
            for (int c = 0; c < 4; c++) acc[i][j][c] = 0.0f;

    for (int it = 0; it < NIT; ++it) {
        const int s = it & 1;
        const int u = it >> 1;
        mwait(mbF[s], u & 1);
        const uint32_t stb = sb + (uint32_t)s * PST_B;

#pragma unroll
        for (int kt = 0; kt < 4; ++kt) {
            uint32_t ah[2][4], al[2][4];
#pragma unroll
            for (int mt = 0; mt < 2; mt++) {
                const int row = wm * 32 + mt * 16 + l16;
                const uint32_t off = (uint32_t)(row * 128) +
                    (((uint32_t)(kt * 32 + hi16)) ^ ((uint32_t)(row & 7) << 4));
                ldsm4(ah[mt], stb + off);
                ldsm4(al[mt], stb + 16384u + off);
            }
#pragma unroll
            for (int np = 0; np < 2; ++np) {
                const int row = wn * 32 + np * 16 + l16;
                const uint32_t off = (uint32_t)(row * 128) +
                    (((uint32_t)(kt * 32 + hi16)) ^ ((uint32_t)(row & 7) << 4));
                uint32_t bh4[4], bl4[4];
                ldsm4(bh4, stb + 32768u + off);
                ldsm4(bl4, stb + 40960u + off);
#pragma unroll
                for (int mt = 0; mt < 2; mt++)
#pragma unroll
                    for (int e = 0; e < 2; e++) {
                        float* c = acc[mt][np * 2 + e];
                        mmaf16(c, ah[mt], bh4[e], bh4[2 + e]);
                        mmaf16(c, ah[mt], bl4[e], bl4[2 + e]);
                        mmaf16(c, al[mt], bh4[e], bh4[2 + e]);
                    }
            }
        }
        __syncwarp();
        if (lane == 0) mbar_arrive(mbE[s]);
    }

    // Epilogue
#pragma unroll
    for (int mt = 0; mt < 2; ++mt) {
#pragma unroll
        for (int nt = 0; nt < 4; ++nt) {
            const int n   = n0 + wn * 32 + nt * 8 + tg * 2;
            const float b0v = bias[n];
            const float b1v = bias[n + 1];
#pragma unroll
            for (int hh = 0; hh < 2; ++hh) {
                const int m  = m0 + wm * 32 + mt * 16 + g + hh * 8;
                const float v0 = acc[mt][nt][hh * 2 + 0] + b0v;
                const float v1 = acc[mt][nt][hh * 2 + 1] + b1v;
                if (MODE == 0) {
                    *(float2*)&Cf[(size_t)m * Dc + n] = make_float2(v0, v1);
                } else {
                    const float s0 = v0 * scale;
                    const float s1 = v1 * scale;
                    const int bb = m >> 11;
                    const int ss = m & (Sc - 1);
                    const int hd = n >> 6;
                    const int dk = n & 63;
                    const int bh = bb * Hc + hd;
                    const __half h0 = __float2half_rn(s0);
                    const __half h1 = __float2half_rn(s1);
                    size_t byteoff;
                    if (MODE == 1) {
                        byteoff = ((size_t)(bh * 16 + (ss >> 7))) * TILE_B +
                                  sw128((uint32_t)((ss & 127) * 128 + dk * 2));
                    } else {
                        byteoff = ((size_t)(bh * 32 + (ss >> 6))) * KVT_B +
                                  sw128((uint32_t)((ss & 63) * 128 + dk * 2));
                    }
                    *(uint32_t*)((char*)Ch + byteoff) = packh2(h0, h1);
                    *(uint32_t*)((char*)Cl + byteoff) =
                        packh2(__float2half_rn(s0 - __half2float(h0)),
                               __float2half_rn(s1 - __half2float(h1)));
                }
            }
        }
    }
}

__global__ __launch_bounds__(288, 2) void qkv_mma_kernel(
    const float* __restrict__ bq, const float* __restrict__ bk,
    const float* __restrict__ bv) {
    const int z = blockIdx.z;
    const __half* Ahi = g_xh + (size_t)z * AMAT;
    const __half* Alo = g_xl + (size_t)z * AMAT;
    const __half* Bhi = g_wh + (size_t)z * WMAT;
    const __half* Blo = g_wl + (size_t)z * WMAT;
    if (z == 0)   // Q pre-scaled by (1/8)*log2(e): softmax uses exp2
        gemm_mma<1>(Ahi, Alo, Bhi, Blo, bq, nullptr, g_qh, g_ql,
                    0.125f * 1.4426950408889634f);
    else if (z == 1)
        gemm_mma<2>(Ahi, Alo, Bhi, Blo, bk, nullptr, g_kh, g_kl, 1.0f);
    else
        gemm_mma<2>(Ahi, Alo, Bhi, Blo, bv, nullptr, g_vh, g_vl, 1.0f);
}

__global__ __launch_bounds__(288, 2) void out_mma_kernel(
    const float* __restrict__ bo, float* __restrict__ out) {
    gemm_mma<0>(g_oh, g_ol, g_wh + 3 * WMAT, g_wl + 3 * WMAT, bo,
                out, nullptr, nullptr, 1.0f);
}

// ---------------------------------------------------------------------------
// Conversions → blocked + SW128-swizzled 128-row tile layout (proven R8).
// ---------------------------------------------------------------------------
__global__ __launch_bounds__(256) void conv_act_kernel(
    const float* __restrict__ q, const float* __restrict__ k,
    const float* __restrict__ v) {
    const int z = blockIdx.y;
    const float* src = (z == 0) ? q : (z == 1) ? k : v;
    const size_t i4 = ((size_t)blockIdx.x * 256 + threadIdx.x) * 4;
    const float4 x = *(const float4*)(src + i4);
    const __half h0 = __float2half_rn(x.x), h1 = __float2half_rn(x.y);
    const __half h2 = __float2half_rn(x.z), h3 = __float2half_rn(x.w);
    uint2 hv, lv;
    hv.x = packh2(h0, h1);
    hv.y = packh2(h2, h3);
    lv.x = packh2(__float2half_rn(x.x - __half2float(h0)),
                  __float2half_rn(x.y - __half2float(h1)));
    lv.y = packh2(__float2half_rn(x.z - __half2float(h2)),
                  __float2half_rn(x.w - __half2float(h3)));
    const int m  = (int)(i4 >> 10);
    const int kk = (int)(i4 & 1023);
    const size_t tile = (size_t)z * 512 + (size_t)(m >> 7) * 16 + (kk >> 6);
    const uint32_t inner = sw128((uint32_t)((m & 127) * 128 + (kk & 63) * 2));
    *(uint2*)((char*)g_xh + tile * TILE_B + inner) = hv;
    *(uint2*)((char*)g_xl + tile * TILE_B + inner) = lv;
}

__global__ __launch_bounds__(256) void conv_w_kernel(
    const float* __restrict__ Wq, const float* __restrict__ Wk,
    const float* __restrict__ Wv, const float* __restrict__ Wo) {
    __shared__ float t[32][33];
    const int z = blockIdx.z;
    const float* W = (z == 0) ? Wq : (z == 1) ? Wk : (z == 2) ? Wv : Wo;
    const int k0 = blockIdx.y << 5;
    const int n0 = blockIdx.x << 5;
    const int tx = threadIdx.x & 31;
    const int ty = threadIdx.x >> 5;
#pragma unroll
    for (int j = 0; j < 4; j++)
        t[ty + j * 8][tx] = W[(size_t)(k0 + ty + j * 8) * Dc + n0 + tx];
    __syncthreads();
#pragma unroll
    for (int j = 0; j < 4; j++) {
        const float val = t[tx][ty + j * 8];
        const __half hv = __float2half_rn(val);
        const int n = n0 + ty + j * 8;
        const int kk = k0 + tx;
        const size_t tile = (size_t)z * 128 + (size_t)(n >> 7) * 16 + (kk >> 6);
        const uint32_t inner = sw128((uint32_t)((n & 127) * 128 + (kk & 63) * 2));
        *(__half*)((char*)g_wh + tile * TILE_B + inner) = hv;
        *(__half*)((char*)g_wl + tile * TILE_B + inner) =
            __float2half_rn(val - __half2float(hv));
    }
}

// ---------------------------------------------------------------------------
// Flash attention — R11 version verbatim (single sacc; the R12 software
// pipeline spilled registers and regressed). mma.sync fp16 3-term,
// producer-warp 4-stage ring, maxless exp2 softmax.
// ---------------------------------------------------------------------------
constexpr int ANS = 4;
constexpr int ATT_SMEM = 32768 + ANS * 32768;   // 163840

__global__ __launch_bounds__(288, 1) void attn_mma_kernel() {
    extern __shared__ char smemraw[];
    const uint32_t sb = smem_u32(smemraw);
    __shared__ uint64_t mbarS[2 * ANS + 1];
    uint32_t mbF[ANS], mbE[ANS];
#pragma unroll
    for (int i = 0; i < ANS; i++) {
        mbF[i] = smem_u32(&mbarS[i]);
        mbE[i] = smem_u32(&mbarS[ANS + i]);
    }
    const uint32_t mbQ = smem_u32(&mbarS[2 * ANS]);

    const int tid  = threadIdx.x;
    const int wid  = tid >> 5;
    const int lane = tid & 31;
    const int bh   = blockIdx.y;
    const int q0b  = blockIdx.x;

    if (tid == 0) {
#pragma unroll
        for (int i = 0; i < ANS; i++) {
            mbar_init(mbF[i], 1);
            mbar_init(mbE[i], 8);
        }
        mbar_init(mbQ, 1);
        fence_async_sh();
    }
    __syncthreads();

    if (wid == 8) {
        if (lane == 0) {
            const size_t qt = ((size_t)(bh * 16 + q0b)) * TILE_B;
            mbar_expect_tx(mbQ, 2 * TILE_B);
            bulk_ld(sb,           (char*)g_qh + qt, TILE_B, mbQ);
            bulk_ld(sb + TILE_B,  (char*)g_ql + qt, TILE_B, mbQ);
            for (int kb = 0; kb < 32; ++kb) {
                const int s = kb & (ANS - 1);
                const int u = kb >> 2;
                if (u > 0) mwait(mbE[s], (u - 1) & 1);
                const uint32_t stb = sb + 32768u + (uint32_t)s * 32768u;
                const size_t t = ((size_t)(bh * 32 + kb)) * KVT_B;
                mbar_expect_tx(mbF[s], 4 * KVT_B);
                bulk_ld(stb,              (char*)g_kh + t, KVT_B, mbF[s]);
                bulk_ld(stb + KVT_B,      (char*)g_kl + t, KVT_B, mbF[s]);
                bulk_ld(stb + 2 * KVT_B,  (char*)g_vh + t, KVT_B, mbF[s]);
                bulk_ld(stb + 3 * KVT_B,  (char*)g_vl + t, KVT_B, mbF[s]);
            }
        }
        return;
    }

    const int g    = lane >> 2;
    const int tg   = lane & 3;
    const int l16  = lane & 15;
    const int hi16 = (lane >> 4) * 16;

    // Q fragments
    mwait(mbQ, 0);
    uint32_t qh[4][4], ql[4][4];
    {
        const int row = wid * 16 + l16;
#pragma unroll
        for (int kt = 0; kt < 4; kt++) {
            const uint32_t off = (uint32_t)(row * 128) +
                (((uint32_t)(kt * 32 + hi16)) ^ ((uint32_t)(row & 7) << 4));
            ldsm4(qh[kt], sb + off);
            ldsm4(ql[kt], sb + TILE_B + off);
        }
    }

    float lrow[2] = {0.0f, 0.0f};
    float O[8][4];
#pragma unroll
    for (int nt = 0; nt < 8; nt++)
#pragma unroll
        for (int c = 0; c < 4; c++) O[nt][c] = 0.0f;

    for (int kb = 0; kb < 32; ++kb) {
        const int s = kb & (ANS - 1);
        const int u = kb >> 2;
        mwait(mbF[s], u & 1);
        const uint32_t stb = sb + 32768u + (uint32_t)s * 32768u;

        // ---- S = Q @ K^T (3-term; log2e-scaled scores) ----
        float sacc[8][4];
#pragma unroll
        for (int nt = 0; nt < 8; nt++)
#pragma unroll
            for (int c = 0; c < 4; c++) sacc[nt][c] = 0.0f;

#pragma unroll
        for (int kt = 0; kt < 4; kt++) {
#pragma unroll
            for (int np = 0; np < 4; np++) {
                const int row = np * 16 + l16;
                const uint32_t off = (uint32_t)(row * 128) +
                    (((uint32_t)(kt * 32 + hi16)) ^ ((uint32_t)(row & 7) << 4));
                uint32_t kh4[4], kl4[4];
                ldsm4(kh4, stb + off);
                ldsm4(kl4, stb + KVT_B + off);
#pragma unroll
                for (int e = 0; e < 2; e++) {
                    float* c = sacc[np * 2 + e];
                    mmaf16(c, qh[kt], kh4[e], kh4[2 + e]);
                    mmaf16(c, qh[kt], kl4[e], kl4[2 + e]);
                    mmaf16(c, ql[kt], kh4[e], kh4[2 + e]);
                }
            }
        }

        // ---- softmax numerators (no max subtraction) ----
#pragma unroll
        for (int r = 0; r < 2; r++) {
            float rs = 0.0f;
#pragma unroll
            for (int nt = 0; nt < 8; nt++) {
                const float e0 = exp2f(sacc[nt][r * 2]);
                const float e1 = exp2f(sacc[nt][r * 2 + 1]);
                sacc[nt][r * 2]     = e0;
                sacc[nt][r * 2 + 1] = e1;
                rs += e0 + e1;
            }
            rs += __shfl_xor_sync(0xffffffffu, rs, 1);
            rs += __shfl_xor_sync(0xffffffffu, rs, 2);
            lrow[r] += rs;
        }

        // ---- pack P (hi/lo) as A fragments ----
        uint32_t pph[4][4], ppl[4][4];
#pragma unroll
        for (int kt = 0; kt < 4; kt++) {
            const float* s0 = sacc[kt * 2];
            const float* s1 = sacc[kt * 2 + 1];
            const float v[4][2] = {
                { s0[0], s0[1] }, { s0[2], s0[3] },
                { s1[0], s1[1] }, { s1[2], s1[3] },
            };
#pragma unroll
            for (int a = 0; a < 4; a++) {
                const __half h0 = __float2half_rn(v[a][0]);
                const __half h1 = __float2half_rn(v[a][1]);
                pph[kt][a] = packh2(h0, h1);
                ppl[kt][a] = packh2(__float2half_rn(v[a][0] - __half2float(h0)),
                                    __float2half_rn(v[a][1] - __half2float(h1)));
            }
        }

        // ---- O += P @ V (3-term), V via ldmatrix.trans ----
#pragma unroll
        for (int kt = 0; kt < 4; kt++) {
#pragma unroll
            for (int np = 0; np < 4; np++) {
                const int row = kt * 16 + l16;
                const uint32_t off = (uint32_t)(row * 128) +
                    (((uint32_t)(np * 32 + hi16)) ^ ((uint32_t)(row & 7) << 4));
                uint32_t vh4[4], vl4[4];
                ldsm4t(vh4, stb + 2 * KVT_B + off);
                ldsm4t(vl4, stb + 3 * KVT_B + off);
#pragma unroll
                for (int e = 0; e < 2; e++) {
                    float* c = O[np * 2 + e];
                    mmaf16(c, pph[kt], vh4[e * 2], vh4[e * 2 + 1]);
                    mmaf16(c, pph[kt], vl4[e * 2], vl4[e * 2 + 1]);
                    mmaf16(c, ppl[kt], vh4[e * 2], vh4[e * 2 + 1]);
                }
            }
        }
        __syncwarp();
        if (lane == 0) mbar_arrive(mbE[s]);
    }

    // ---- write O as split fp16 into BLOCKED layout (out-proj A operand) ----
    const int b = bh >> 4;
    const int h = bh & 15;
#pragma unroll
    for (int r = 0; r < 2; r++) {
        const float inv = 1.0f / lrow[r];
        const int row = q0b * 128 + wid * 16 + g + r * 8;
        const int m   = b * Sc + row;
        const size_t tbase = ((size_t)(m >> 7) * 16 + h) * TILE_B;
        const uint32_t rbase = (uint32_t)((m & 127) * 128);
        const uint32_t xm    = (uint32_t)((m & 7) << 4);
#pragma unroll
        for (int nt = 0; nt < 8; nt++) {
            const int c = nt * 8 + tg * 2;
            const uint32_t inner = rbase + (((uint32_t)(c * 2)) ^ xm);
            const float v0 = O[nt][r * 2]     * inv;
            const float v1 = O[nt][r * 2 + 1] * inv;
            const __half h0 = __float2half_rn(v0);
            const __half h1 = __float2half_rn(v1);
            *(uint32_t*)((char*)g_oh + tbase + inner) = packh2(h0, h1);
            *(uint32_t*)((char*)g_ol + tbase + inner) =
                packh2(__float2half_rn(v0 - __half2float(h0)),
                       __float2half_rn(v1 - __half2float(h1)));
        }
    }
}

// ---------------------------------------------------------------------------
// Inputs: q,k,v,mask,Wq,bq,Wk,bk,Wv,bv,Wo,bo (mask inert, as in reference)
// ---------------------------------------------------------------------------
extern "C" void kernel_launch(void* const* d_in, const int* in_sizes, int n_in,
                              void* d_out, int out_size) {
    (void)in_sizes; (void)n_in; (void)out_size;
    const float* q  = (const float*)d_in[0];
    const float* k  = (const float*)d_in[1];
    const float* v  = (const float*)d_in[2];
    const float* Wq = (const float*)d_in[4];
    const float* bq = (const float*)d_in[5];
    const float* Wk = (const float*)d_in[6];
    const float* bk = (const float*)d_in[7];
    const float* Wv = (const float*)d_in[8];
    const float* bv = (const float*)d_in[9];
    const float* Wo = (const float*)d_in[10];
    const float* bo = (const float*)d_in[11];
    float* out = (float*)d_out;

    static bool attr_set = false;
    if (!attr_set) {
        cudaFuncSetAttribute(attn_mma_kernel,
                             cudaFuncAttributeMaxDynamicSharedMemorySize, ATT_SMEM);
        cudaFuncSetAttribute(qkv_mma_kernel,
                             cudaFuncAttributeMaxDynamicSharedMemorySize, PSMEM);
        cudaFuncSetAttribute(out_mma_kernel,
                             cudaFuncAttributeMaxDynamicSharedMemorySize, PSMEM);
        attr_set = true;
    }

    conv_act_kernel<<<dim3((unsigned)(AMAT / 1024), 3), 256>>>(q, k, v);
    conv_w_kernel<<<dim3(32, 32, 4), 256>>>(Wq, Wk, Wv, Wo);

    qkv_mma_kernel<<<dim3(16, 32, 3), 288, PSMEM>>>(bq, bk, bv);
    attn_mma_kernel<<<dim3(16, 32), 288, ATT_SMEM>>>();
    out_mma_kernel<<<dim3(16, 32), 288, PSMEM>>>(bo, out);
}

// round 14
// speedup vs baseline: 1.1688x; 1.0623x over previous
#include <cuda_runtime.h>
#include <cuda_fp16.h>
#include <cstdint>

constexpr int Bc  = 2;
constexpr int Sc  = 2048;
constexpr int Dc  = 1024;
constexpr int Hc  = 16;
constexpr int DKc = 64;
constexpr int Mtot = Bc * Sc;                       // 4096
constexpr size_t AMAT = (size_t)Mtot * Dc;          // 4M elems
constexpr size_t WMAT = (size_t)Dc * Dc;            // 1M elems
constexpr int TILE_B  = 16384;                      // 128 rows x 64 halfs x 2B
constexpr int KVT_B   = 8192;                       // 64 rows x 64 halfs x 2B

// Scratch (device globals) — all operands blocked + SW128-swizzled
__device__ __half g_xh[3 * AMAT], g_xl[3 * AMAT];   // split inputs (128-row tiles)
__device__ __half g_wh[4 * WMAT], g_wl[4 * WMAT];   // split weights [n][k] (128-row tiles)
__device__ __half g_oh[AMAT], g_ol[AMAT];           // attention out [b,s,d] (128-row tiles)
__device__ __half g_qh[AMAT], g_ql[AMAT];           // Q (x 0.125*log2e) 128-row tiles
__device__ __half g_kh[AMAT], g_kl[AMAT];           // K [bh, sblock] 64-row tiles
__device__ __half g_vh[AMAT], g_vl[AMAT];           // V [bh, sblock] 64-row tiles

// ---------------------------------------------------------------------------
// PTX helpers
// ---------------------------------------------------------------------------
__device__ __forceinline__ uint32_t smem_u32(const void* p) {
    uint32_t a;
    asm("{ .reg .u64 t; cvta.to.shared.u64 t, %1; cvt.u32.u64 %0, t; }" : "=r"(a) : "l"(p));
    return a;
}
__device__ __forceinline__ uint32_t sw128(uint32_t x) { return x ^ ((x >> 3) & 0x70); }

__device__ __forceinline__ void bulk_ld(uint32_t dst, const void* src, uint32_t bytes,
                                        uint32_t mbar) {
    asm volatile(
        "cp.async.bulk.shared::cluster.global.mbarrier::complete_tx::bytes "
        "[%0], [%1], %2, [%3];"
        :: "r"(dst), "l"(src), "r"(bytes), "r"(mbar) : "memory");
}
__device__ __forceinline__ void mbar_init(uint32_t a, uint32_t cnt) {
    asm volatile("mbarrier.init.shared.b64 [%0], %1;" :: "r"(a), "r"(cnt) : "memory");
}
__device__ __forceinline__ void mbar_expect_tx(uint32_t a, uint32_t bytes) {
    asm volatile("mbarrier.arrive.expect_tx.shared.b64 _, [%0], %1;"
                 :: "r"(a), "r"(bytes) : "memory");
}
__device__ __forceinline__ void mbar_arrive(uint32_t a) {
    asm volatile("mbarrier.arrive.shared.b64 _, [%0];" :: "r"(a) : "memory");
}
__device__ __forceinline__ void mwait(uint32_t mbar, uint32_t parity) {
    asm volatile(
        "{\n\t.reg .pred P;\n\t"
        "WL%=:\n\t"
        "mbarrier.try_wait.parity.acquire.cta.shared::cta.b64 P, [%0], %1, 0x989680;\n\t"
        "@!P bra WL%=;\n\t}"
        :: "r"(mbar), "r"(parity) : "memory");
}
__device__ __forceinline__ void fence_async_sh() {
    asm volatile("fence.proxy.async.shared::cta;" ::: "memory");
}

__device__ __forceinline__ void ldsm4(uint32_t r[4], uint32_t addr) {
    asm volatile("ldmatrix.sync.aligned.m8n8.x4.shared.b16 {%0,%1,%2,%3}, [%4];"
                 : "=r"(r[0]), "=r"(r[1]), "=r"(r[2]), "=r"(r[3]) : "r"(addr));
}
__device__ __forceinline__ void ldsm4t(uint32_t r[4], uint32_t addr) {
    asm volatile("ldmatrix.sync.aligned.m8n8.x4.trans.shared.b16 {%0,%1,%2,%3}, [%4];"
                 : "=r"(r[0]), "=r"(r[1]), "=r"(r[2]), "=r"(r[3]) : "r"(addr));
}
__device__ __forceinline__ void mmaf16(float* c, const uint32_t a[4],
                                       uint32_t b0, uint32_t b1) {
    asm volatile("mma.sync.aligned.m16n8k16.row.col.f32.f16.f16.f32 "
                 "{%0,%1,%2,%3}, {%4,%5,%6,%7}, {%8,%9}, {%0,%1,%2,%3};"
                 : "+f"(c[0]), "+f"(c[1]), "+f"(c[2]), "+f"(c[3])
                 : "r"(a[0]), "r"(a[1]), "r"(a[2]), "r"(a[3]), "r"(b0), "r"(b1));
}
__device__ __forceinline__ uint32_t packh2(__half a, __half b) {
    __half2 h = __halves2half2(a, b);
    return *(uint32_t*)&h;
}

// ---------------------------------------------------------------------------
// Split-fp16 mma.sync GEMM, producer-warp pipeline (R12 WIN — kept).
// CTA 128(M) x 64(N), BK=64, 2 stages x 48KB = 96KB → 2 CTAs/SM.
// MODE 0: fp32 row-major. MODE 1: Q blocked (scaled). MODE 2: K/V blocked.
// ---------------------------------------------------------------------------
constexpr int PNS    = 2;
constexpr int PST_B  = 49152;            // 48KB per stage
constexpr int PSMEM  = PNS * PST_B;      // 98304

template <int MODE>
__device__ __forceinline__ void gemm_mma(const __half* __restrict__ Ahi,
                                         const __half* __restrict__ Alo,
                                         const __half* __restrict__ Bhi,
                                         const __half* __restrict__ Blo,
                                         const float* __restrict__ bias,
                                         float* __restrict__ Cf,
                                         __half* __restrict__ Ch,
                                         __half* __restrict__ Cl,
                                         float scale) {
    extern __shared__ char smemraw[];
    const uint32_t sb = smem_u32(smemraw);
    __shared__ uint64_t mbarS[2 * PNS];
    uint32_t mbF[PNS], mbE[PNS];
#pragma unroll
    for (int i = 0; i < PNS; i++) {
        mbF[i] = smem_u32(&mbarS[i]);
        mbE[i] = smem_u32(&mbarS[PNS + i]);
    }

    const int tid  = threadIdx.x;
    const int wid  = tid >> 5;
    const int lane = tid & 31;
    const int m0   = blockIdx.y << 7;
    const int n0   = blockIdx.x << 6;

    if (tid == 0) {
#pragma unroll
        for (int i = 0; i < PNS; i++) {
            mbar_init(mbF[i], 1);
            mbar_init(mbE[i], 8);
        }
        fence_async_sh();
    }
    __syncthreads();

    const int NIT = Dc / 64;   // 16

    if (wid == 8) {
        if (lane == 0) {
            for (int it = 0; it < NIT; ++it) {
                const int s = it & 1;
                const int u = it >> 1;
                if (u > 0) mwait(mbE[s], (u - 1) & 1);
                const uint32_t stb = sb + (uint32_t)s * PST_B;
                const size_t at = ((size_t)blockIdx.y * 16 + it) * TILE_B;
                const size_t bt = ((size_t)((n0 >> 7) * 16 + it)) * TILE_B +
                                  (size_t)((n0 & 64) << 7);
                mbar_expect_tx(mbF[s], 2 * TILE_B + 2 * KVT_B);
                bulk_ld(stb,          (const char*)Ahi + at, TILE_B, mbF[s]);
                bulk_ld(stb + 16384u, (const char*)Alo + at, TILE_B, mbF[s]);
                bulk_ld(stb + 32768u, (const char*)Bhi + bt, KVT_B, mbF[s]);
                bulk_ld(stb + 40960u, (const char*)Blo + bt, KVT_B, mbF[s]);
            }
        }
        return;
    }

    const int g    = lane >> 2;
    const int tg   = lane & 3;
    const int wm   = wid & 3;            // 4 warps over M (32 rows each)
    const int wn   = wid >> 2;           // 2 warps over N (32 cols each)
    const int l16  = lane & 15;
    const int hi16 = (lane >> 4) * 16;

    float acc[2][4][4];
#pragma unroll
    for (int i = 0; i < 2; i++)
#pragma unroll
        for (int j = 0; j < 4; j++)
#pragma unroll
            for (int c = 0; c < 4; c++) acc[i][j][c] = 0.0f;

    for (int it = 0; it < NIT; ++it) {
        const int s = it & 1;
        const int u = it >> 1;
        mwait(mbF[s], u & 1);
        const uint32_t stb = sb + (uint32_t)s * PST_B;

#pragma unroll
        for (int kt = 0; kt < 4; ++kt) {
            uint32_t ah[2][4], al[2][4];
#pragma unroll
            for (int mt = 0; mt < 2; mt++) {
                const int row = wm * 32 + mt * 16 + l16;
                const uint32_t off = (uint32_t)(row * 128) +
                    (((uint32_t)(kt * 32 + hi16)) ^ ((uint32_t)(row & 7) << 4));
                ldsm4(ah[mt], stb + off);
                ldsm4(al[mt], stb + 16384u + off);
            }
#pragma unroll
            for (int np = 0; np < 2; ++np) {
                const int row = wn * 32 + np * 16 + l16;
                const uint32_t off = (uint32_t)(row * 128) +
                    (((uint32_t)(kt * 32 + hi16)) ^ ((uint32_t)(row & 7) << 4));
                uint32_t bh4[4], bl4[4];
                ldsm4(bh4, stb + 32768u + off);
                ldsm4(bl4, stb + 40960u + off);
#pragma unroll
                for (int mt = 0; mt < 2; mt++)
#pragma unroll
                    for (int e = 0; e < 2; e++) {
                        float* c = acc[mt][np * 2 + e];
                        mmaf16(c, ah[mt], bh4[e], bh4[2 + e]);
                        mmaf16(c, ah[mt], bl4[e], bl4[2 + e]);
                        mmaf16(c, al[mt], bh4[e], bh4[2 + e]);
                    }
            }
        }
        __syncwarp();
        if (lane == 0) mbar_arrive(mbE[s]);
    }

    // Epilogue
#pragma unroll
    for (int mt = 0; mt < 2; ++mt) {
#pragma unroll
        for (int nt = 0; nt < 4; ++nt) {
            const int n   = n0 + wn * 32 + nt * 8 + tg * 2;
            const float b0v = bias[n];
            const float b1v = bias[n + 1];
#pragma unroll
            for (int hh = 0; hh < 2; ++hh) {
                const int m  = m0 + wm * 32 + mt * 16 + g + hh * 8;
                const float v0 = acc[mt][nt][hh * 2 + 0] + b0v;
                const float v1 = acc[mt][nt][hh * 2 + 1] + b1v;
                if (MODE == 0) {
                    *(float2*)&Cf[(size_t)m * Dc + n] = make_float2(v0, v1);
                } else {
                    const float s0 = v0 * scale;
                    const float s1 = v1 * scale;
                    const int bb = m >> 11;
                    const int ss = m & (Sc - 1);
                    const int hd = n >> 6;
                    const int dk = n & 63;
                    const int bh = bb * Hc + hd;
                    const __half h0 = __float2half_rn(s0);
                    const __half h1 = __float2half_rn(s1);
                    size_t byteoff;
                    if (MODE == 1) {
                        byteoff = ((size_t)(bh * 16 + (ss >> 7))) * TILE_B +
                                  sw128((uint32_t)((ss & 127) * 128 + dk * 2));
                    } else {
                        byteoff = ((size_t)(bh * 32 + (ss >> 6))) * KVT_B +
                                  sw128((uint32_t)((ss & 63) * 128 + dk * 2));
                    }
                    *(uint32_t*)((char*)Ch + byteoff) = packh2(h0, h1);
                    *(uint32_t*)((char*)Cl + byteoff) =
                        packh2(__float2half_rn(s0 - __half2float(h0)),
                               __float2half_rn(s1 - __half2float(h1)));
                }
            }
        }
    }
}

__global__ __launch_bounds__(288, 2) void qkv_mma_kernel(
    const float* __restrict__ bq, const float* __restrict__ bk,
    const float* __restrict__ bv) {
    const int z = blockIdx.z;
    const __half* Ahi = g_xh + (size_t)z * AMAT;
    const __half* Alo = g_xl + (size_t)z * AMAT;
    const __half* Bhi = g_wh + (size_t)z * WMAT;
    const __half* Blo = g_wl + (size_t)z * WMAT;
    if (z == 0)   // Q pre-scaled by (1/8)*log2(e): softmax uses exp2
        gemm_mma<1>(Ahi, Alo, Bhi, Blo, bq, nullptr, g_qh, g_ql,
                    0.125f * 1.4426950408889634f);
    else if (z == 1)
        gemm_mma<2>(Ahi, Alo, Bhi, Blo, bk, nullptr, g_kh, g_kl, 1.0f);
    else
        gemm_mma<2>(Ahi, Alo, Bhi, Blo, bv, nullptr, g_vh, g_vl, 1.0f);
}

__global__ __launch_bounds__(288, 2) void out_mma_kernel(
    const float* __restrict__ bo, float* __restrict__ out) {
    gemm_mma<0>(g_oh, g_ol, g_wh + 3 * WMAT, g_wl + 3 * WMAT, bo,
                out, nullptr, nullptr, 1.0f);
}

// ---------------------------------------------------------------------------
// Conversions → blocked + SW128-swizzled 128-row tile layout (proven R8).
// ---------------------------------------------------------------------------
__global__ __launch_bounds__(256) void conv_act_kernel(
    const float* __restrict__ q, const float* __restrict__ k,
    const float* __restrict__ v) {
    const int z = blockIdx.y;
    const float* src = (z == 0) ? q : (z == 1) ? k : v;
    const size_t i4 = ((size_t)blockIdx.x * 256 + threadIdx.x) * 4;
    const float4 x = *(const float4*)(src + i4);
    const __half h0 = __float2half_rn(x.x), h1 = __float2half_rn(x.y);
    const __half h2 = __float2half_rn(x.z), h3 = __float2half_rn(x.w);
    uint2 hv, lv;
    hv.x = packh2(h0, h1);
    hv.y = packh2(h2, h3);
    lv.x = packh2(__float2half_rn(x.x - __half2float(h0)),
                  __float2half_rn(x.y - __half2float(h1)));
    lv.y = packh2(__float2half_rn(x.z - __half2float(h2)),
                  __float2half_rn(x.w - __half2float(h3)));
    const int m  = (int)(i4 >> 10);
    const int kk = (int)(i4 & 1023);
    const size_t tile = (size_t)z * 512 + (size_t)(m >> 7) * 16 + (kk >> 6);
    const uint32_t inner = sw128((uint32_t)((m & 127) * 128 + (kk & 63) * 2));
    *(uint2*)((char*)g_xh + tile * TILE_B + inner) = hv;
    *(uint2*)((char*)g_xl + tile * TILE_B + inner) = lv;
}

__global__ __launch_bounds__(256) void conv_w_kernel(
    const float* __restrict__ Wq, const float* __restrict__ Wk,
    const float* __restrict__ Wv, const float* __restrict__ Wo) {
    __shared__ float t[32][33];
    const int z = blockIdx.z;
    const float* W = (z == 0) ? Wq : (z == 1) ? Wk : (z == 2) ? Wv : Wo;
    const int k0 = blockIdx.y << 5;
    const int n0 = blockIdx.x << 5;
    const int tx = threadIdx.x & 31;
    const int ty = threadIdx.x >> 5;
#pragma unroll
    for (int j = 0; j < 4; j++)
        t[ty + j * 8][tx] = W[(size_t)(k0 + ty + j * 8) * Dc + n0 + tx];
    __syncthreads();
#pragma unroll
    for (int j = 0; j < 4; j++) {
        const float val = t[tx][ty + j * 8];
        const __half hv = __float2half_rn(val);
        const int n = n0 + ty + j * 8;
        const int kk = k0 + tx;
        const size_t tile = (size_t)z * 128 + (size_t)(n >> 7) * 16 + (kk >> 6);
        const uint32_t inner = sw128((uint32_t)((n & 127) * 128 + (kk & 63) * 2));
        *(__half*)((char*)g_wh + tile * TILE_B + inner) = hv;
        *(__half*)((char*)g_wl + tile * TILE_B + inner) =
            __float2half_rn(val - __half2float(hv));
    }
}

// ---------------------------------------------------------------------------
// Flash attention — occupancy retile of the proven R11/R13 kernel.
// CTA: 64 q-rows, 5 warps (4 compute + 1 producer), 160 threads.
// Smem: Qh 8KB + Ql 8KB + 3 KV stages x 32KB = 112KB → 2 CTAs/SM.
// Per-warp work identical to R13 (16 q-rows, same fragments/softmax).
// Q 64-row block = contiguous 8KB half of a 128-row blocked tile.
// ---------------------------------------------------------------------------
constexpr int ANS = 3;
constexpr int ATT_SMEM = 16384 + ANS * 32768;   // 114688

__global__ __launch_bounds__(160, 2) void attn_mma_kernel() {
    extern __shared__ char smemraw[];
    const uint32_t sb = smem_u32(smemraw);
    __shared__ uint64_t mbarS[2 * ANS + 1];
    uint32_t mbF[ANS], mbE[ANS];
#pragma unroll
    for (int i = 0; i < ANS; i++) {
        mbF[i] = smem_u32(&mbarS[i]);
        mbE[i] = smem_u32(&mbarS[ANS + i]);
    }
    const uint32_t mbQ = smem_u32(&mbarS[2 * ANS]);

    const int tid  = threadIdx.x;
    const int wid  = tid >> 5;
    const int lane = tid & 31;
    const int bh   = blockIdx.y;
    const int q0b  = blockIdx.x;         // 64-row q block index (0..31)

    if (tid == 0) {
#pragma unroll
        for (int i = 0; i < ANS; i++) {
            mbar_init(mbF[i], 1);
            mbar_init(mbE[i], 4);        // 4 compute warps
        }
        mbar_init(mbQ, 1);
        fence_async_sh();
    }
    __syncthreads();

    if (wid == 4) {
        // ---- producer warp ----
        if (lane == 0) {
            // Q 64-row block: contiguous 8KB half of 128-row tile
            const size_t qt = ((size_t)(bh * 16 + (q0b >> 1))) * TILE_B +
                              (size_t)(q0b & 1) * 8192;
            mbar_expect_tx(mbQ, 2 * 8192);
            bulk_ld(sb,         (char*)g_qh + qt, 8192, mbQ);
            bulk_ld(sb + 8192u, (char*)g_ql + qt, 8192, mbQ);
            for (int kb = 0; kb < 32; ++kb) {
                const int s = kb % ANS;
                const int u = kb / ANS;
                if (u > 0) mwait(mbE[s], (u - 1) & 1);
                const uint32_t stb = sb + 16384u + (uint32_t)s * 32768u;
                const size_t t = ((size_t)(bh * 32 + kb)) * KVT_B;
                mbar_expect_tx(mbF[s], 4 * KVT_B);
                bulk_ld(stb,              (char*)g_kh + t, KVT_B, mbF[s]);
                bulk_ld(stb + KVT_B,      (char*)g_kl + t, KVT_B, mbF[s]);
                bulk_ld(stb + 2 * KVT_B,  (char*)g_vh + t, KVT_B, mbF[s]);
                bulk_ld(stb + 3 * KVT_B,  (char*)g_vl + t, KVT_B, mbF[s]);
            }
        }
        return;
    }

    // ---- compute warps (0-3), 16 q-rows each ----
    const int g    = lane >> 2;
    const int tg   = lane & 3;
    const int l16  = lane & 15;
    const int hi16 = (lane >> 4) * 16;

    // Q fragments
    mwait(mbQ, 0);
    uint32_t qh[4][4], ql[4][4];
    {
        const int row = wid * 16 + l16;      // 0..63
#pragma unroll
        for (int kt = 0; kt < 4; kt++) {
            const uint32_t off = (uint32_t)(row * 128) +
                (((uint32_t)(kt * 32 + hi16)) ^ ((uint32_t)(row & 7) << 4));
            ldsm4(qh[kt], sb + off);
            ldsm4(ql[kt], sb + 8192u + off);
        }
    }

    float lrow[2] = {0.0f, 0.0f};
    float O[8][4];
#pragma unroll
    for (int nt = 0; nt < 8; nt++)
#pragma unroll
        for (int c = 0; c < 4; c++) O[nt][c] = 0.0f;

    for (int kb = 0; kb < 32; ++kb) {
        const int s = kb % ANS;
        const int u = kb / ANS;
        mwait(mbF[s], u & 1);
        const uint32_t stb = sb + 16384u + (uint32_t)s * 32768u;

        // ---- S = Q @ K^T (3-term; log2e-scaled scores) ----
        float sacc[8][4];
#pragma unroll
        for (int nt = 0; nt < 8; nt++)
#pragma unroll
            for (int c = 0; c < 4; c++) sacc[nt][c] = 0.0f;

#pragma unroll
        for (int kt = 0; kt < 4; kt++) {
#pragma unroll
            for (int np = 0; np < 4; np++) {
                const int row = np * 16 + l16;
                const uint32_t off = (uint32_t)(row * 128) +
                    (((uint32_t)(kt * 32 + hi16)) ^ ((uint32_t)(row & 7) << 4));
                uint32_t kh4[4], kl4[4];
                ldsm4(kh4, stb + off);
                ldsm4(kl4, stb + KVT_B + off);
#pragma unroll
                for (int e = 0; e < 2; e++) {
                    float* c = sacc[np * 2 + e];
                    mmaf16(c, qh[kt], kh4[e], kh4[2 + e]);
                    mmaf16(c, qh[kt], kl4[e], kl4[2 + e]);
                    mmaf16(c, ql[kt], kh4[e], kh4[2 + e]);
                }
            }
        }

        // ---- softmax numerators (no max subtraction) ----
#pragma unroll
        for (int r = 0; r < 2; r++) {
            float rs = 0.0f;
#pragma unroll
            for (int nt = 0; nt < 8; nt++) {
                const float e0 = exp2f(sacc[nt][r * 2]);
                const float e1 = exp2f(sacc[nt][r * 2 + 1]);
                sacc[nt][r * 2]     = e0;
                sacc[nt][r * 2 + 1] = e1;
                rs += e0 + e1;
            }
            rs += __shfl_xor_sync(0xffffffffu, rs, 1);
            rs += __shfl_xor_sync(0xffffffffu, rs, 2);
            lrow[r] += rs;
        }

        // ---- pack P (hi/lo) as A fragments ----
        uint32_t pph[4][4], ppl[4][4];
#pragma unroll
        for (int kt = 0; kt < 4; kt++) {
            const float* s0 = sacc[kt * 2];
            const float* s1 = sacc[kt * 2 + 1];
            const float v[4][2] = {
                { s0[0], s0[1] }, { s0[2], s0[3] },
                { s1[0], s1[1] }, { s1[2], s1[3] },
            };
#pragma unroll
            for (int a = 0; a < 4; a++) {
                const __half h0 = __float2half_rn(v[a][0]);
                const __half h1 = __float2half_rn(v[a][1]);
                pph[kt][a] = packh2(h0, h1);
                ppl[kt][a] = packh2(__float2half_rn(v[a][0] - __half2float(h0)),
                                    __float2half_rn(v[a][1] - __half2float(h1)));
            }
        }

        // ---- O += P @ V (3-term), V via ldmatrix.trans ----
#pragma unroll
        for (int kt = 0; kt < 4; kt++) {
#pragma unroll
            for (int np = 0; np < 4; np++) {
                const int row = kt * 16 + l16;
                const uint32_t off = (uint32_t)(row * 128) +
                    (((uint32_t)(np * 32 + hi16)) ^ ((uint32_t)(row & 7) << 4));
                uint32_t vh4[4], vl4[4];
                ldsm4t(vh4, stb + 2 * KVT_B + off);
                ldsm4t(vl4, stb + 3 * KVT_B + off);
#pragma unroll
                for (int e = 0; e < 2; e++) {
                    float* c = O[np * 2 + e];
                    mmaf16(c, pph[kt], vh4[e * 2], vh4[e * 2 + 1]);
                    mmaf16(c, pph[kt], vl4[e * 2], vl4[e * 2 + 1]);
                    mmaf16(c, ppl[kt], vh4[e * 2], vh4[e * 2 + 1]);
                }
            }
        }
        __syncwarp();
        if (lane == 0) mbar_arrive(mbE[s]);
    }

    // ---- write O as split fp16 into BLOCKED layout (out-proj A operand) ----
    const int b = bh >> 4;
    const int h = bh & 15;
#pragma unroll
    for (int r = 0; r < 2; r++) {
        const float inv = 1.0f / lrow[r];
        const int row = q0b * 64 + wid * 16 + g + r * 8;
        const int m   = b * Sc + row;
        const size_t tbase = ((size_t)(m >> 7) * 16 + h) * TILE_B;
        const uint32_t rbase = (uint32_t)((m & 127) * 128);
        const uint32_t xm    = (uint32_t)((m & 7) << 4);
#pragma unroll
        for (int nt = 0; nt < 8; nt++) {
            const int c = nt * 8 + tg * 2;
            const uint32_t inner = rbase + (((uint32_t)(c * 2)) ^ xm);
            const float v0 = O[nt][r * 2]     * inv;
            const float v1 = O[nt][r * 2 + 1] * inv;
            const __half h0 = __float2half_rn(v0);
            const __half h1 = __float2half_rn(v1);
            *(uint32_t*)((char*)g_oh + tbase + inner) = packh2(h0, h1);
            *(uint32_t*)((char*)g_ol + tbase + inner) =
                packh2(__float2half_rn(v0 - __half2float(h0)),
                       __float2half_rn(v1 - __half2float(h1)));
        }
    }
}

// ---------------------------------------------------------------------------
// Inputs: q,k,v,mask,Wq,bq,Wk,bk,Wv,bv,Wo,bo (mask inert, as in reference)
// ---------------------------------------------------------------------------
extern "C" void kernel_launch(void* const* d_in, const int* in_sizes, int n_in,
                              void* d_out, int out_size) {
    (void)in_sizes; (void)n_in; (void)out_size;
    const float* q  = (const float*)d_in[0];
    const float* k  = (const float*)d_in[1];
    const float* v  = (const float*)d_in[2];
    const float* Wq = (const float*)d_in[4];
    const float* bq = (const float*)d_in[5];
    const float* Wk = (const float*)d_in[6];
    const float* bk = (const float*)d_in[7];
    const float* Wv = (const float*)d_in[8];
    const float* bv = (const float*)d_in[9];
    const float* Wo = (const float*)d_in[10];
    const float* bo = (const float*)d_in[11];
    float* out = (float*)d_out;

    static bool attr_set = false;
    if (!attr_set) {
        cudaFuncSetAttribute(attn_mma_kernel,
                             cudaFuncAttributeMaxDynamicSharedMemorySize, ATT_SMEM);
        cudaFuncSetAttribute(qkv_mma_kernel,
                             cudaFuncAttributeMaxDynamicSharedMemorySize, PSMEM);
        cudaFuncSetAttribute(out_mma_kernel,
                             cudaFuncAttributeMaxDynamicSharedMemorySize, PSMEM);
        attr_set = true;
    }

    conv_act_kernel<<<dim3((unsigned)(AMAT / 1024), 3), 256>>>(q, k, v);
    conv_w_kernel<<<dim3(32, 32, 4), 256>>>(Wq, Wk, Wv, Wo);

    qkv_mma_kernel<<<dim3(16, 32, 3), 288, PSMEM>>>(bq, bk, bv);
    attn_mma_kernel<<<dim3(32, 32), 160, ATT_SMEM>>>();
    out_mma_kernel<<<dim3(16, 32), 288, PSMEM>>>(bo, out);
}

// round 15
// speedup vs baseline: 1.5824x; 1.3539x over previous
#include <cuda_runtime.h>
#include <cuda_fp16.h>
#include <cstdint>

constexpr int Bc  = 2;
constexpr int Sc  = 2048;
constexpr int Dc  = 1024;
constexpr int Hc  = 16;
constexpr int DKc = 64;
constexpr int Mtot = Bc * Sc;                       // 4096
constexpr size_t AMAT = (size_t)Mtot * Dc;          // 4M elems
constexpr size_t WMAT = (size_t)Dc * Dc;            // 1M elems
constexpr int TILE_B  = 16384;                      // 128 rows x 64 halfs x 2B
constexpr int KVT_B   = 8192;                       // 64 rows x 64 halfs x 2B

// Scratch (device globals) — all operands blocked + SW128-swizzled.
// Split scheme: every product A·B ≈ Ah·(Bh+Bl): only B-side keeps a low half.
__device__ __half g_xh[3 * AMAT];                   // inputs, hi only (128-row tiles)
__device__ __half g_wh[4 * WMAT], g_wl[4 * WMAT];   // weights [n][k] hi+lo (128-row tiles)
__device__ __half g_oh[AMAT];                       // attention out hi only (128-row tiles)
__device__ __half g_qh[AMAT];                       // Q hi only (x 0.125*log2e), 128-row tiles
__device__ __half g_kh[AMAT], g_kl[AMAT];           // K hi+lo, 64-row tiles
__device__ __half g_vh[AMAT], g_vl[AMAT];           // V hi+lo, 64-row tiles

// ---------------------------------------------------------------------------
// PTX helpers
// ---------------------------------------------------------------------------
__device__ __forceinline__ uint32_t smem_u32(const void* p) {
    uint32_t a;
    asm("{ .reg .u64 t; cvta.to.shared.u64 t, %1; cvt.u32.u64 %0, t; }" : "=r"(a) : "l"(p));
    return a;
}
__device__ __forceinline__ uint32_t sw128(uint32_t x) { return x ^ ((x >> 3) & 0x70); }

__device__ __forceinline__ void bulk_ld(uint32_t dst, const void* src, uint32_t bytes,
                                        uint32_t mbar) {
    asm volatile(
        "cp.async.bulk.shared::cluster.global.mbarrier::complete_tx::bytes "
        "[%0], [%1], %2, [%3];"
        :: "r"(dst), "l"(src), "r"(bytes), "r"(mbar) : "memory");
}
__device__ __forceinline__ void mbar_init(uint32_t a, uint32_t cnt) {
    asm volatile("mbarrier.init.shared.b64 [%0], %1;" :: "r"(a), "r"(cnt) : "memory");
}
__device__ __forceinline__ void mbar_expect_tx(uint32_t a, uint32_t bytes) {
    asm volatile("mbarrier.arrive.expect_tx.shared.b64 _, [%0], %1;"
                 :: "r"(a), "r"(bytes) : "memory");
}
__device__ __forceinline__ void mbar_arrive(uint32_t a) {
    asm volatile("mbarrier.arrive.shared.b64 _, [%0];" :: "r"(a) : "memory");
}
__device__ __forceinline__ void mwait(uint32_t mbar, uint32_t parity) {
    asm volatile(
        "{\n\t.reg .pred P;\n\t"
        "WL%=:\n\t"
        "mbarrier.try_wait.parity.acquire.cta.shared::cta.b64 P, [%0], %1, 0x989680;\n\t"
        "@!P bra WL%=;\n\t}"
        :: "r"(mbar), "r"(parity) : "memory");
}
__device__ __forceinline__ void fence_async_sh() {
    asm volatile("fence.proxy.async.shared::cta;" ::: "memory");
}

__device__ __forceinline__ void ldsm4(uint32_t r[4], uint32_t addr) {
    asm volatile("ldmatrix.sync.aligned.m8n8.x4.shared.b16 {%0,%1,%2,%3}, [%4];"
                 : "=r"(r[0]), "=r"(r[1]), "=r"(r[2]), "=r"(r[3]) : "r"(addr));
}
__device__ __forceinline__ void ldsm4t(uint32_t r[4], uint32_t addr) {
    asm volatile("ldmatrix.sync.aligned.m8n8.x4.trans.shared.b16 {%0,%1,%2,%3}, [%4];"
                 : "=r"(r[0]), "=r"(r[1]), "=r"(r[2]), "=r"(r[3]) : "r"(addr));
}
__device__ __forceinline__ void mmaf16(float* c, const uint32_t a[4],
                                       uint32_t b0, uint32_t b1) {
    asm volatile("mma.sync.aligned.m16n8k16.row.col.f32.f16.f16.f32 "
                 "{%0,%1,%2,%3}, {%4,%5,%6,%7}, {%8,%9}, {%0,%1,%2,%3};"
                 : "+f"(c[0]), "+f"(c[1]), "+f"(c[2]), "+f"(c[3])
                 : "r"(a[0]), "r"(a[1]), "r"(a[2]), "r"(a[3]), "r"(b0), "r"(b1));
}
__device__ __forceinline__ uint32_t packh2(__half a, __half b) {
    __half2 h = __halves2half2(a, b);
    return *(uint32_t*)&h;
}

// ---------------------------------------------------------------------------
// 2-term split GEMM: C = Ah @ (Wh + Wl)^T + bias. Producer-warp pipeline.
// CTA 128(M) x 64(N), BK=64, 3 stages x 32KB = 96KB → 2 CTAs/SM.
// Stage: Ahi 16KB | Bhi 8KB | Blo 8KB.
// MODE 0: fp32 row-major. MODE 1: Q blocked hi-only (scaled).
// MODE 2: K/V blocked hi+lo.
// ---------------------------------------------------------------------------
constexpr int PNS    = 3;
constexpr int PST_B  = 32768;            // 32KB per stage
constexpr int PSMEM  = PNS * PST_B;      // 98304

template <int MODE>
__device__ __forceinline__ void gemm_mma(const __half* __restrict__ Ahi,
                                         const __half* __restrict__ Bhi,
                                         const __half* __restrict__ Blo,
                                         const float* __restrict__ bias,
                                         float* __restrict__ Cf,
                                         __half* __restrict__ Ch,
                                         __half* __restrict__ Cl,
                                         float scale) {
    extern __shared__ char smemraw[];
    const uint32_t sb = smem_u32(smemraw);
    __shared__ uint64_t mbarS[2 * PNS];
    uint32_t mbF[PNS], mbE[PNS];
#pragma unroll
    for (int i = 0; i < PNS; i++) {
        mbF[i] = smem_u32(&mbarS[i]);
        mbE[i] = smem_u32(&mbarS[PNS + i]);
    }

    const int tid  = threadIdx.x;
    const int wid  = tid >> 5;
    const int lane = tid & 31;
    const int m0   = blockIdx.y << 7;
    const int n0   = blockIdx.x << 6;

    if (tid == 0) {
#pragma unroll
        for (int i = 0; i < PNS; i++) {
            mbar_init(mbF[i], 1);
            mbar_init(mbE[i], 8);
        }
        fence_async_sh();
    }
    __syncthreads();

    const int NIT = Dc / 64;   // 16

    if (wid == 8) {
        if (lane == 0) {
            for (int it = 0; it < NIT; ++it) {
                const int s = it % PNS;
                const int u = it / PNS;
                if (u > 0) mwait(mbE[s], (u - 1) & 1);
                const uint32_t stb = sb + (uint32_t)s * PST_B;
                const size_t at = ((size_t)blockIdx.y * 16 + it) * TILE_B;
                const size_t bt = ((size_t)((n0 >> 7) * 16 + it)) * TILE_B +
                                  (size_t)((n0 & 64) << 7);
                mbar_expect_tx(mbF[s], TILE_B + 2 * KVT_B);
                bulk_ld(stb,          (const char*)Ahi + at, TILE_B, mbF[s]);
                bulk_ld(stb + 16384u, (const char*)Bhi + bt, KVT_B, mbF[s]);
                bulk_ld(stb + 24576u, (const char*)Blo + bt, KVT_B, mbF[s]);
            }
        }
        return;
    }

    const int g    = lane >> 2;
    const int tg   = lane & 3;
    const int wm   = wid & 3;            // 4 warps over M (32 rows each)
    const int wn   = wid >> 2;           // 2 warps over N (32 cols each)
    const int l16  = lane & 15;
    const int hi16 = (lane >> 4) * 16;

    float acc[2][4][4];
#pragma unroll
    for (int i = 0; i < 2; i++)
#pragma unroll
        for (int j = 0; j < 4; j++)
#pragma unroll
            for (int c = 0; c < 4; c++) acc[i][j][c] = 0.0f;

    for (int it = 0; it < NIT; ++it) {
        const int s = it % PNS;
        const int u = it / PNS;
        mwait(mbF[s], u & 1);
        const uint32_t stb = sb + (uint32_t)s * PST_B;

#pragma unroll
        for (int kt = 0; kt < 4; ++kt) {
            uint32_t ah[2][4];
#pragma unroll
            for (int mt = 0; mt < 2; mt++) {
                const int row = wm * 32 + mt * 16 + l16;
                const uint32_t off = (uint32_t)(row * 128) +
                    (((uint32_t)(kt * 32 + hi16)) ^ ((uint32_t)(row & 7) << 4));
                ldsm4(ah[mt], stb + off);
            }
#pragma unroll
            for (int np = 0; np < 2; ++np) {
                const int row = wn * 32 + np * 16 + l16;
                const uint32_t off = (uint32_t)(row * 128) +
                    (((uint32_t)(kt * 32 + hi16)) ^ ((uint32_t)(row & 7) << 4));
                uint32_t bh4[4], bl4[4];
                ldsm4(bh4, stb + 16384u + off);
                ldsm4(bl4, stb + 24576u + off);
#pragma unroll
                for (int mt = 0; mt < 2; mt++)
#pragma unroll
                    for (int e = 0; e < 2; e++) {
                        float* c = acc[mt][np * 2 + e];
                        mmaf16(c, ah[mt], bh4[e], bh4[2 + e]);
                        mmaf16(c, ah[mt], bl4[e], bl4[2 + e]);
                    }
            }
        }
        __syncwarp();
        if (lane == 0) mbar_arrive(mbE[s]);
    }

    // Epilogue
#pragma unroll
    for (int mt = 0; mt < 2; ++mt) {
#pragma unroll
        for (int nt = 0; nt < 4; ++nt) {
            const int n   = n0 + wn * 32 + nt * 8 + tg * 2;
            const float b0v = bias[n];
            const float b1v = bias[n + 1];
#pragma unroll
            for (int hh = 0; hh < 2; ++hh) {
                const int m  = m0 + wm * 32 + mt * 16 + g + hh * 8;
                const float v0 = acc[mt][nt][hh * 2 + 0] + b0v;
                const float v1 = acc[mt][nt][hh * 2 + 1] + b1v;
                if (MODE == 0) {
                    *(float2*)&Cf[(size_t)m * Dc + n] = make_float2(v0, v1);
                } else {
                    const float s0 = v0 * scale;
                    const float s1 = v1 * scale;
                    const int bb = m >> 11;
                    const int ss = m & (Sc - 1);
                    const int hd = n >> 6;
                    const int dk = n & 63;
                    const int bh = bb * Hc + hd;
                    const __half h0 = __float2half_rn(s0);
                    const __half h1 = __float2half_rn(s1);
                    if (MODE == 1) {     // Q: 128-row tiles, hi only
                        const size_t byteoff =
                            ((size_t)(bh * 16 + (ss >> 7))) * TILE_B +
                            sw128((uint32_t)((ss & 127) * 128 + dk * 2));
                        *(uint32_t*)((char*)Ch + byteoff) = packh2(h0, h1);
                    } else {             // K/V: 64-row tiles, hi+lo
                        const size_t byteoff =
                            ((size_t)(bh * 32 + (ss >> 6))) * KVT_B +
                            sw128((uint32_t)((ss & 63) * 128 + dk * 2));
                        *(uint32_t*)((char*)Ch + byteoff) = packh2(h0, h1);
                        *(uint32_t*)((char*)Cl + byteoff) =
                            packh2(__float2half_rn(s0 - __half2float(h0)),
                                   __float2half_rn(s1 - __half2float(h1)));
                    }
                }
            }
        }
    }
}

__global__ __launch_bounds__(288, 2) void qkv_mma_kernel(
    const float* __restrict__ bq, const float* __restrict__ bk,
    const float* __restrict__ bv) {
    const int z = blockIdx.z;
    const __half* Ahi = g_xh + (size_t)z * AMAT;
    const __half* Bhi = g_wh + (size_t)z * WMAT;
    const __half* Blo = g_wl + (size_t)z * WMAT;
    if (z == 0)   // Q pre-scaled by (1/8)*log2(e): softmax uses exp2
        gemm_mma<1>(Ahi, Bhi, Blo, bq, nullptr, g_qh, nullptr,
                    0.125f * 1.4426950408889634f);
    else if (z == 1)
        gemm_mma<2>(Ahi, Bhi, Blo, bk, nullptr, g_kh, g_kl, 1.0f);
    else
        gemm_mma<2>(Ahi, Bhi, Blo, bv, nullptr, g_vh, g_vl, 1.0f);
}

__global__ __launch_bounds__(288, 2) void out_mma_kernel(
    const float* __restrict__ bo, float* __restrict__ out) {
    gemm_mma<0>(g_oh, g_wh + 3 * WMAT, g_wl + 3 * WMAT, bo,
                out, nullptr, nullptr, 1.0f);
}

// ---------------------------------------------------------------------------
// Conversions → blocked + SW128-swizzled 128-row tile layout.
// Activations: hi only (lo side dropped by the 2-term scheme).
// ---------------------------------------------------------------------------
__global__ __launch_bounds__(256) void conv_act_kernel(
    const float* __restrict__ q, const float* __restrict__ k,
    const float* __restrict__ v) {
    const int z = blockIdx.y;
    const float* src = (z == 0) ? q : (z == 1) ? k : v;
    const size_t i4 = ((size_t)blockIdx.x * 256 + threadIdx.x) * 4;
    const float4 x = *(const float4*)(src + i4);
    uint2 hv;
    hv.x = packh2(__float2half_rn(x.x), __float2half_rn(x.y));
    hv.y = packh2(__float2half_rn(x.z), __float2half_rn(x.w));
    const int m  = (int)(i4 >> 10);
    const int kk = (int)(i4 & 1023);
    const size_t tile = (size_t)z * 512 + (size_t)(m >> 7) * 16 + (kk >> 6);
    const uint32_t inner = sw128((uint32_t)((m & 127) * 128 + (kk & 63) * 2));
    *(uint2*)((char*)g_xh + tile * TILE_B + inner) = hv;
}

__global__ __launch_bounds__(256) void conv_w_kernel(
    const float* __restrict__ Wq, const float* __restrict__ Wk,
    const float* __restrict__ Wv, const float* __restrict__ Wo) {
    __shared__ float t[32][33];
    const int z = blockIdx.z;
    const float* W = (z == 0) ? Wq : (z == 1) ? Wk : (z == 2) ? Wv : Wo;
    const int k0 = blockIdx.y << 5;
    const int n0 = blockIdx.x << 5;
    const int tx = threadIdx.x & 31;
    const int ty = threadIdx.x >> 5;
#pragma unroll
    for (int j = 0; j < 4; j++)
        t[ty + j * 8][tx] = W[(size_t)(k0 + ty + j * 8) * Dc + n0 + tx];
    __syncthreads();
#pragma unroll
    for (int j = 0; j < 4; j++) {
        const float val = t[tx][ty + j * 8];
        const __half hv = __float2half_rn(val);
        const int n = n0 + ty + j * 8;
        const int kk = k0 + tx;
        const size_t tile = (size_t)z * 128 + (size_t)(n >> 7) * 16 + (kk >> 6);
        const uint32_t inner = sw128((uint32_t)((n & 127) * 128 + (kk & 63) * 2));
        *(__half*)((char*)g_wh + tile * TILE_B + inner) = hv;
        *(__half*)((char*)g_wl + tile * TILE_B + inner) =
            __float2half_rn(val - __half2float(hv));
    }
}

// ---------------------------------------------------------------------------
// Flash attention — R14 structure (64 q-rows, 4+1 warps, 2 CTAs/SM), now
// 2-term splits: S = Qh·(Kh+Kl), O = Ph·(Vh+Vl). No Q-lo, no P-lo pack.
// Smem: Qh 8KB + 3 KV stages x 32KB = 104KB → 2 CTAs/SM.
// ---------------------------------------------------------------------------
constexpr int ANS = 3;
constexpr int ATT_SMEM = 8192 + ANS * 32768;   // 106496

__global__ __launch_bounds__(160, 2) void attn_mma_kernel() {
    extern __shared__ char smemraw[];
    const uint32_t sb = smem_u32(smemraw);
    __shared__ uint64_t mbarS[2 * ANS + 1];
    uint32_t mbF[ANS], mbE[ANS];
#pragma unroll
    for (int i = 0; i < ANS; i++) {
        mbF[i] = smem_u32(&mbarS[i]);
        mbE[i] = smem_u32(&mbarS[ANS + i]);
    }
    const uint32_t mbQ = smem_u32(&mbarS[2 * ANS]);

    const int tid  = threadIdx.x;
    const int wid  = tid >> 5;
    const int lane = tid & 31;
    const int bh   = blockIdx.y;
    const int q0b  = blockIdx.x;         // 64-row q block index (0..31)

    if (tid == 0) {
#pragma unroll
        for (int i = 0; i < ANS; i++) {
            mbar_init(mbF[i], 1);
            mbar_init(mbE[i], 4);        // 4 compute warps
        }
        mbar_init(mbQ, 1);
        fence_async_sh();
    }
    __syncthreads();

    if (wid == 4) {
        // ---- producer warp ----
        if (lane == 0) {
            // Q 64-row block: contiguous 8KB half of 128-row tile (hi only)
            const size_t qt = ((size_t)(bh * 16 + (q0b >> 1))) * TILE_B +
                              (size_t)(q0b & 1) * 8192;
            mbar_expect_tx(mbQ, 8192);
            bulk_ld(sb, (char*)g_qh + qt, 8192, mbQ);
            for (int kb = 0; kb < 32; ++kb) {
                const int s = kb % ANS;
                const int u = kb / ANS;
                if (u > 0) mwait(mbE[s], (u - 1) & 1);
                const uint32_t stb = sb + 8192u + (uint32_t)s * 32768u;
                const size_t t = ((size_t)(bh * 32 + kb)) * KVT_B;
                mbar_expect_tx(mbF[s], 4 * KVT_B);
                bulk_ld(stb,              (char*)g_kh + t, KVT_B, mbF[s]);
                bulk_ld(stb + KVT_B,      (char*)g_kl + t, KVT_B, mbF[s]);
                bulk_ld(stb + 2 * KVT_B,  (char*)g_vh + t, KVT_B, mbF[s]);
                bulk_ld(stb + 3 * KVT_B,  (char*)g_vl + t, KVT_B, mbF[s]);
            }
        }
        return;
    }

    // ---- compute warps (0-3), 16 q-rows each ----
    const int g    = lane >> 2;
    const int tg   = lane & 3;
    const int l16  = lane & 15;
    const int hi16 = (lane >> 4) * 16;

    // Q fragments (hi only)
    mwait(mbQ, 0);
    uint32_t qh[4][4];
    {
        const int row = wid * 16 + l16;      // 0..63
#pragma unroll
        for (int kt = 0; kt < 4; kt++) {
            const uint32_t off = (uint32_t)(row * 128) +
                (((uint32_t)(kt * 32 + hi16)) ^ ((uint32_t)(row & 7) << 4));
            ldsm4(qh[kt], sb + off);
        }
    }

    float lrow[2] = {0.0f, 0.0f};
    float O[8][4];
#pragma unroll
    for (int nt = 0; nt < 8; nt++)
#pragma unroll
        for (int c = 0; c < 4; c++) O[nt][c] = 0.0f;

    for (int kb = 0; kb < 32; ++kb) {
        const int s = kb % ANS;
        const int u = kb / ANS;
        mwait(mbF[s], u & 1);
        const uint32_t stb = sb + 8192u + (uint32_t)s * 32768u;

        // ---- S = Qh @ (Kh+Kl)^T (log2e-scaled scores) ----
        float sacc[8][4];
#pragma unroll
        for (int nt = 0; nt < 8; nt++)
#pragma unroll
            for (int c = 0; c < 4; c++) sacc[nt][c] = 0.0f;

#pragma unroll
        for (int kt = 0; kt < 4; kt++) {
#pragma unroll
            for (int np = 0; np < 4; np++) {
                const int row = np * 16 + l16;
                const uint32_t off = (uint32_t)(row * 128) +
                    (((uint32_t)(kt * 32 + hi16)) ^ ((uint32_t)(row & 7) << 4));
                uint32_t kh4[4], kl4[4];
                ldsm4(kh4, stb + off);
                ldsm4(kl4, stb + KVT_B + off);
#pragma unroll
                for (int e = 0; e < 2; e++) {
                    float* c = sacc[np * 2 + e];
                    mmaf16(c, qh[kt], kh4[e], kh4[2 + e]);
                    mmaf16(c, qh[kt], kl4[e], kl4[2 + e]);
                }
            }
        }

        // ---- softmax numerators (no max subtraction) ----
#pragma unroll
        for (int r = 0; r < 2; r++) {
            float rs = 0.0f;
#pragma unroll
            for (int nt = 0; nt < 8; nt++) {
                const float e0 = exp2f(sacc[nt][r * 2]);
                const float e1 = exp2f(sacc[nt][r * 2 + 1]);
                sacc[nt][r * 2]     = e0;
                sacc[nt][r * 2 + 1] = e1;
                rs += e0 + e1;
            }
            rs += __shfl_xor_sync(0xffffffffu, rs, 1);
            rs += __shfl_xor_sync(0xffffffffu, rs, 2);
            lrow[r] += rs;
        }

        // ---- pack P (hi only) as A fragments ----
        uint32_t pph[4][4];
#pragma unroll
        for (int kt = 0; kt < 4; kt++) {
            const float* s0 = sacc[kt * 2];
            const float* s1 = sacc[kt * 2 + 1];
            pph[kt][0] = packh2(__float2half_rn(s0[0]), __float2half_rn(s0[1]));
            pph[kt][1] = packh2(__float2half_rn(s0[2]), __float2half_rn(s0[3]));
            pph[kt][2] = packh2(__float2half_rn(s1[0]), __float2half_rn(s1[1]));
            pph[kt][3] = packh2(__float2half_rn(s1[2]), __float2half_rn(s1[3]));
        }

        // ---- O += Ph @ (Vh+Vl), V via ldmatrix.trans ----
#pragma unroll
        for (int kt = 0; kt < 4; kt++) {
#pragma unroll
            for (int np = 0; np < 4; np++) {
                const int row = kt * 16 + l16;
                const uint32_t off = (uint32_t)(row * 128) +
                    (((uint32_t)(np * 32 + hi16)) ^ ((uint32_t)(row & 7) << 4));
                uint32_t vh4[4], vl4[4];
                ldsm4t(vh4, stb + 2 * KVT_B + off);
                ldsm4t(vl4, stb + 3 * KVT_B + off);
#pragma unroll
                for (int e = 0; e < 2; e++) {
                    float* c = O[np * 2 + e];
                    mmaf16(c, pph[kt], vh4[e * 2], vh4[e * 2 + 1]);
                    mmaf16(c, pph[kt], vl4[e * 2], vl4[e * 2 + 1]);
                }
            }
        }
        __syncwarp();
        if (lane == 0) mbar_arrive(mbE[s]);
    }

    // ---- write O (hi only) into BLOCKED layout (out-proj A operand) ----
    const int b = bh >> 4;
    const int h = bh & 15;
#pragma unroll
    for (int r = 0; r < 2; r++) {
        const float inv = 1.0f / lrow[r];
        const int row = q0b * 64 + wid * 16 + g + r * 8;
        const int m   = b * Sc + row;
        const size_t tbase = ((size_t)(m >> 7) * 16 + h) * TILE_B;
        const uint32_t rbase = (uint32_t)((m & 127) * 128);
        const uint32_t xm    = (uint32_t)((m & 7) << 4);
#pragma unroll
        for (int nt = 0; nt < 8; nt++) {
            const int c = nt * 8 + tg * 2;
            const uint32_t inner = rbase + (((uint32_t)(c * 2)) ^ xm);
            *(uint32_t*)((char*)g_oh + tbase + inner) =
                packh2(__float2half_rn(O[nt][r * 2] * inv),
                       __float2half_rn(O[nt][r * 2 + 1] * inv));
        }
    }
}

// ---------------------------------------------------------------------------
// Inputs: q,k,v,mask,Wq,bq,Wk,bk,Wv,bv,Wo,bo (mask inert, as in reference)
// ---------------------------------------------------------------------------
extern "C" void kernel_launch(void* const* d_in, const int* in_sizes, int n_in,
                              void* d_out, int out_size) {
    (void)in_sizes; (void)n_in; (void)out_size;
    const float* q  = (const float*)d_in[0];
    const float* k  = (const float*)d_in[1];
    const float* v  = (const float*)d_in[2];
    const float* Wq = (const float*)d_in[4];
    const float* bq = (const float*)d_in[5];
    const float* Wk = (const float*)d_in[6];
    const float* bk = (const float*)d_in[7];
    const float* Wv = (const float*)d_in[8];
    const float* bv = (const float*)d_in[9];
    const float* Wo = (const float*)d_in[10];
    const float* bo = (const float*)d_in[11];
    float* out = (float*)d_out;

    static bool attr_set = false;
    if (!attr_set) {
        cudaFuncSetAttribute(attn_mma_kernel,
                             cudaFuncAttributeMaxDynamicSharedMemorySize, ATT_SMEM);
        cudaFuncSetAttribute(qkv_mma_kernel,
                             cudaFuncAttributeMaxDynamicSharedMemorySize, PSMEM);
        cudaFuncSetAttribute(out_mma_kernel,
                             cudaFuncAttributeMaxDynamicSharedMemorySize, PSMEM);
        attr_set = true;
    }

    conv_act_kernel<<<dim3((unsigned)(AMAT / 1024), 3), 256>>>(q, k, v);
    conv_w_kernel<<<dim3(32, 32, 4), 256>>>(Wq, Wk, Wv, Wo);

    qkv_mma_kernel<<<dim3(16, 32, 3), 288, PSMEM>>>(bq, bk, bv);
    attn_mma_kernel<<<dim3(32, 32), 160, ATT_SMEM>>>();
    out_mma_kernel<<<dim3(16, 32), 288, PSMEM>>>(bo, out);
}